// round 11
// baseline (speedup 1.0000x reference)
#include <cuda_runtime.h>
#include <cuda_fp16.h>
#include <math.h>
#include <cstdint>

#define B_  2
#define S_  2048
#define D_  2048
#define H_  16
#define KV_ 4
#define HD_ 128
#define NQKV 3072   // 2048 q + 512 k + 512 v

// ---------------------------------------------------------------------------
// Helpers (base-target instructions only: ldmatrix / mma.sync / cp.async)
// ---------------------------------------------------------------------------
__device__ __forceinline__ uint32_t smem_to_u32(const void* smem_ptr) {
    uint32_t addr;
    asm("{ .reg .u64 tmp; cvta.to.shared.u64 tmp, %1; cvt.u32.u64 %0, tmp; }"
        : "=r"(addr) : "l"(smem_ptr));
    return addr;
}
__device__ __forceinline__ void cp_async16(uint32_t s, const void* g) {
    asm volatile("cp.async.cg.shared.global [%0], [%1], 16;" :: "r"(s), "l"(g));
}
__device__ __forceinline__ void ldsm4(uint32_t* r, uint32_t addr) {
    asm volatile("ldmatrix.sync.aligned.m8n8.x4.shared.b16 {%0,%1,%2,%3}, [%4];"
        : "=r"(r[0]), "=r"(r[1]), "=r"(r[2]), "=r"(r[3]) : "r"(addr));
}
__device__ __forceinline__ void ldsm4t(uint32_t* r, uint32_t addr) {
    asm volatile("ldmatrix.sync.aligned.m8n8.x4.trans.shared.b16 {%0,%1,%2,%3}, [%4];"
        : "=r"(r[0]), "=r"(r[1]), "=r"(r[2]), "=r"(r[3]) : "r"(addr));
}
// fp16 MMA, fp32 accumulate
__device__ __forceinline__ void mma16816(float* d, const uint32_t* a, const uint32_t* b) {
    asm volatile(
        "mma.sync.aligned.m16n8k16.row.col.f32.f16.f16.f32 "
        "{%0,%1,%2,%3}, {%4,%5,%6,%7}, {%8,%9}, {%0,%1,%2,%3};"
        : "+f"(d[0]), "+f"(d[1]), "+f"(d[2]), "+f"(d[3])
        : "r"(a[0]), "r"(a[1]), "r"(a[2]), "r"(a[3]), "r"(b[0]), "r"(b[1]));
}
__device__ __forceinline__ uint32_t pack_h2(float lo, float hi) {
    __half2 t = __floats2half2_rn(lo, hi);
    return *(uint32_t*)&t;
}
__device__ __forceinline__ float ex2f(float x) {
    float r; asm("ex2.approx.f32 %0, %1;" : "=f"(r) : "f"(x)); return r;
}

// ---------------------------------------------------------------------------
// Scratch (allocation-free rule: device globals)
// ---------------------------------------------------------------------------
__device__ float g_q[B_*H_*S_*HD_];     // fp32 pre-RoPE
__device__ float g_k[B_*KV_*S_*HD_];    // fp32 pre-RoPE

__device__ __half g_xh[B_*S_*D_], g_xl[B_*S_*D_];
__device__ __half g_wqkvt[NQKV*D_];
__device__ __half g_wot[D_*D_];
__device__ __half g_ah[B_*S_*H_*HD_], g_al[B_*S_*H_*HD_];

__device__ __half g_qh[B_*H_*S_*HD_], g_ql[B_*H_*S_*HD_];
__device__ __half g_kf[B_*KV_*S_*HD_];
__device__ __half g_vf[B_*KV_*S_*HD_];

__device__ float2 g_rope[S_ * (HD_/2)];

// ---------------------------------------------------------------------------
// Elementwise fp32 -> (hi, lo) fp16 split.
// ---------------------------------------------------------------------------
__global__ __launch_bounds__(256) void split_kernel(
    const float4* __restrict__ in, __half2* __restrict__ oh,
    __half2* __restrict__ ol, int n4)
{
    int i = blockIdx.x * blockDim.x + threadIdx.x;
    if (i >= n4) return;
    float4 v = in[i];
    float vs[4] = {v.x, v.y, v.z, v.w};
    float hh[4];
    #pragma unroll
    for (int j = 0; j < 4; j++) hh[j] = __half2float(__float2half_rn(vs[j]));
    oh[2*i]   = __floats2half2_rn(hh[0], hh[1]);
    oh[2*i+1] = __floats2half2_rn(hh[2], hh[3]);
    ol[2*i]   = __floats2half2_rn(vs[0] - hh[0], vs[1] - hh[1]);
    ol[2*i+1] = __floats2half2_rn(vs[2] - hh[2], vs[3] - hh[3]);
}

// ---------------------------------------------------------------------------
// ALL weight transposes in ONE launch: fp32 [K,N] -> single fp16 [N,K].
// ---------------------------------------------------------------------------
__global__ void transpose_all_kernel(
    const float* __restrict__ wq, const float* __restrict__ wk,
    const float* __restrict__ wv, const float* __restrict__ wo,
    __half* __restrict__ qkv, __half* __restrict__ wot)
{
    const int z = blockIdx.z;
    const float* in;
    __half* oh;
    int N;
    if (z == 0)      { in = wq; oh = qkv;                     N = 2048; }
    else if (z == 1) { in = wk; oh = qkv + (size_t)2048 * D_; N = 512; }
    else if (z == 2) { in = wv; oh = qkv + (size_t)2560 * D_; N = 512; }
    else             { in = wo; oh = wot;                     N = 2048; }
    if (blockIdx.x * 32 >= N) return;

    __shared__ float tile[32][33];
    int tx = threadIdx.x, ty = threadIdx.y;
    int n0 = blockIdx.x * 32, k0 = blockIdx.y * 32;
    #pragma unroll
    for (int j = 0; j < 32; j += 8)
        tile[ty + j][tx] = in[(size_t)(k0 + ty + j) * N + n0 + tx];
    __syncthreads();
    #pragma unroll
    for (int j = 0; j < 32; j += 8) {
        float v = tile[tx][ty + j];
        oh[(size_t)(n0 + ty + j) * D_ + k0 + tx] = __float2half_rn(v);
    }
}

// ---------------------------------------------------------------------------
// RoPE table: fp64 phase + two-term 2pi range reduction + HW sincosf.
// ---------------------------------------------------------------------------
__global__ __launch_bounds__(256) void rope_table_kernel()
{
    int idx = blockIdx.x * blockDim.x + threadIdx.x;
    if (idx >= S_ * (HD_/2)) return;
    int i = idx & 63, pos = idx >> 6;
    const double LOG2_THETA = 18.93156856932417108;   // log2(500000)
    double inv = exp2(-((double)i / 64.0) * LOG2_THETA);
    double f = (double)pos * inv;
    const double TWO_PI_HI = 6.283185307179586;
    const double TWO_PI_LO = 2.4492935982947064e-16;
    double n = rint(f * 0.15915494309189535);
    double r = f - n * TWO_PI_HI;
    r = r - n * TWO_PI_LO;
    float rc, rs;
    __sincosf((float)r, &rs, &rc);
    g_rope[idx] = make_float2(rc, rs);
}

// ---------------------------------------------------------------------------
// GEMM mainloop: 128x128 CTA tile, 256 threads, BK=32, THREE-stage cp.async
// pipeline with a single __syncthreads per chunk. fp16 2-product.
// ---------------------------------------------------------------------------
#define PITCH 40
#define TILE_B (128 * PITCH * 2)        // 10240
#define OFF_AH 0
#define OFF_AL TILE_B
#define OFF_BF (2 * TILE_B)
#define STAGE_SZ (3 * TILE_B)           // 30720
#define MM_SMEM_BYTES (3 * STAGE_SZ)    // 92160

__device__ __forceinline__ void gemm_mainloop(
    const __half* __restrict__ Ah, const __half* __restrict__ Al,
    const __half* __restrict__ Bf,
    int K, int row0, int col0, uint32_t su, int tid, float acc[2][8][4])
{
    const int wid = tid >> 5, lane = tid & 31;
    const int warp_m = wid & 3, warp_n = wid >> 2;

    const int nchunks = K >> 5;

    auto prefetch = [&](int ck, int stg) {
        const int k0 = ck << 5;
        const uint32_t sb = su + stg * STAGE_SZ;
        #pragma unroll
        for (int h = 0; h < 2; h++) {
            int c = tid + h * 256;
            int r = c >> 2, kc = c & 3;
            uint32_t so = (uint32_t)(r * PITCH * 2 + kc * 16);
            size_t ga = (size_t)(row0 + r) * K + k0 + kc * 8;
            size_t gb = (size_t)(col0 + r) * K + k0 + kc * 8;
            cp_async16(sb + OFF_AH + so, Ah + ga);
            cp_async16(sb + OFF_AL + so, Al + ga);
            cp_async16(sb + OFF_BF + so, Bf + gb);
        }
        asm volatile("cp.async.commit_group;");
    };

    const int r8 = lane & 7, grp = lane >> 3;
    const int a_r = (grp & 1) * 8 + r8;
    const int a_c = (grp >> 1) * 8;
    const int b_r = (grp >> 1) * 8 + r8;
    const int b_c = (grp & 1) * 8;

    prefetch(0, 0);
    prefetch(1, 1);
    int st = 0, st2 = 2;
    for (int ck = 0; ck < nchunks; ck++) {
        if (ck < nchunks - 1) asm volatile("cp.async.wait_group 1;");
        else                  asm volatile("cp.async.wait_group 0;");
        __syncthreads();
        if (ck + 2 < nchunks) prefetch(ck + 2, st2);

        const uint32_t sb = su + st * STAGE_SZ;
        #pragma unroll
        for (int ks = 0; ks < 2; ks++) {
            const int klo = ks * 16;
            uint32_t afh[2][4], afl[2][4], bf[4][4];
            #pragma unroll
            for (int mt = 0; mt < 2; mt++) {
                uint32_t ao = ((warp_m * 32 + mt * 16 + a_r) * PITCH + klo + a_c) * 2;
                ldsm4(afh[mt], sb + OFF_AH + ao);
                ldsm4(afl[mt], sb + OFF_AL + ao);
            }
            #pragma unroll
            for (int np = 0; np < 4; np++)
                ldsm4(bf[np], sb + OFF_BF +
                      ((warp_n * 64 + np * 16 + b_r) * PITCH + klo + b_c) * 2);
            // P1: Ah * Bf
            #pragma unroll
            for (int np = 0; np < 4; np++)
                #pragma unroll
                for (int mt = 0; mt < 2; mt++) {
                    mma16816(acc[mt][2*np],   afh[mt], bf[np]);
                    mma16816(acc[mt][2*np+1], afh[mt], bf[np] + 2);
                }
            // P2: Al * Bf (B reused from registers)
            #pragma unroll
            for (int np = 0; np < 4; np++)
                #pragma unroll
                for (int mt = 0; mt < 2; mt++) {
                    mma16816(acc[mt][2*np],   afl[mt], bf[np]);
                    mma16816(acc[mt][2*np+1], afl[mt], bf[np] + 2);
                }
        }
        st  = (st  == 2) ? 0 : st  + 1;
        st2 = (st2 == 2) ? 0 : st2 + 1;
    }
    __syncthreads();   // protect smem before epilogue reuse / kernel end
}

// ---------------------------------------------------------------------------
// Merged QKV projection GEMM (V fp16 rounding fused into epilogue).
// ---------------------------------------------------------------------------
__global__ __launch_bounds__(256, 2) void hmma_qkv_kernel(
    const __half* __restrict__ Ah, const __half* __restrict__ Al,
    const __half* __restrict__ Bf)
{
    extern __shared__ char smem[];
    const uint32_t su = smem_to_u32(smem);
    const int tid = threadIdx.x;
    const int wid = tid >> 5, lane = tid & 31;
    const int warp_m = wid & 3, warp_n = wid >> 2;
    const int row0 = blockIdx.y * 128, col0 = blockIdx.x * 128;

    float acc[2][8][4];
    #pragma unroll
    for (int i = 0; i < 2; i++)
        #pragma unroll
        for (int j = 0; j < 8; j++)
            #pragma unroll
            for (int k = 0; k < 4; k++) acc[i][j][k] = 0.0f;

    gemm_mainloop(Ah, Al, Bf, D_, row0, col0, su, tid, acc);

    const int r4 = lane >> 2, c2 = (lane & 3) * 2;
    const int region = (col0 < 2048) ? 0 : (col0 < 2560 ? 1 : 2);
    #pragma unroll
    for (int mt = 0; mt < 2; mt++) {
        #pragma unroll
        for (int half = 0; half < 2; half++) {
            int m = row0 + warp_m * 32 + mt * 16 + half * 8 + r4;
            int bb = m >> 11;
            int s  = m & (S_ - 1);
            #pragma unroll
            for (int nt = 0; nt < 8; nt++) {
                int n = col0 + warp_n * 64 + nt * 8 + c2;
                float vx = acc[mt][nt][half * 2 + 0];
                float vy = acc[mt][nt][half * 2 + 1];
                if (region == 0) {
                    int hh = n >> 7, d = n & 127;
                    float2 v = {vx, vy};
                    *(float2*)&g_q[(((size_t)bb * H_ + hh) * S_ + s) * HD_ + d] = v;
                } else if (region == 1) {
                    int nn = n - 2048;
                    int hh = nn >> 7, d = nn & 127;
                    float2 v = {vx, vy};
                    *(float2*)&g_k[(((size_t)bb * KV_ + hh) * S_ + s) * HD_ + d] = v;
                } else {
                    int nn = n - 2560;
                    int hh = nn >> 7, d = nn & 127;
                    size_t o = (((size_t)bb * KV_ + hh) * S_ + s) * HD_ + d;
                    *(__half2*)&g_vf[o] = __floats2half2_rn(vx, vy);
                }
            }
        }
    }
}

// ---------------------------------------------------------------------------
// Output projection GEMM: plain row-major fp32 store into d_out.
// ---------------------------------------------------------------------------
__global__ __launch_bounds__(256, 2) void hmma_oproj_kernel(
    const __half* __restrict__ Ah, const __half* __restrict__ Al,
    const __half* __restrict__ Bf, float* __restrict__ C)
{
    extern __shared__ char smem[];
    const uint32_t su = smem_to_u32(smem);
    const int tid = threadIdx.x;
    const int wid = tid >> 5, lane = tid & 31;
    const int warp_m = wid & 3, warp_n = wid >> 2;
    const int row0 = blockIdx.y * 128, col0 = blockIdx.x * 128;

    float acc[2][8][4];
    #pragma unroll
    for (int i = 0; i < 2; i++)
        #pragma unroll
        for (int j = 0; j < 8; j++)
            #pragma unroll
            for (int k = 0; k < 4; k++) acc[i][j][k] = 0.0f;

    gemm_mainloop(Ah, Al, Bf, D_, row0, col0, su, tid, acc);

    const int r4 = lane >> 2, c2 = (lane & 3) * 2;
    #pragma unroll
    for (int mt = 0; mt < 2; mt++) {
        #pragma unroll
        for (int half = 0; half < 2; half++) {
            int m = row0 + warp_m * 32 + mt * 16 + half * 8 + r4;
            #pragma unroll
            for (int nt = 0; nt < 8; nt++) {
                int n = col0 + warp_n * 64 + nt * 8 + c2;
                float2 v;
                v.x = acc[mt][nt][half * 2 + 0];
                v.y = acc[mt][nt][half * 2 + 1];
                *(float2*)&C[(size_t)m * D_ + n] = v;
            }
        }
    }
}

// ---------------------------------------------------------------------------
// RoPE + convert: Q -> fp16 hi/lo, K -> single fp16.
// ---------------------------------------------------------------------------
__global__ __launch_bounds__(256) void rope_split_kernel(const int* __restrict__ pos_ids)
{
    const int NQP = B_ * H_  * S_ * (HD_ / 2);
    const int NKP = B_ * KV_ * S_ * (HD_ / 2);
    int idx = blockIdx.x * blockDim.x + threadIdx.x;
    bool isQ;
    const float* src;
    int nh;
    if (idx < NQP) { src = g_q; nh = H_; isQ = true; }
    else if (idx < NQP + NKP) { src = g_k; nh = KV_; idx -= NQP; isQ = false; }
    else return;

    int i  = idx & 63;
    int s  = (idx >> 6) & (S_ - 1);
    int bh = idx >> 17;
    int b  = bh / nh;
    int pos = pos_ids[b * S_ + s];

    float2 cs = g_rope[pos * 64 + i];
    float c = cs.x, sn = cs.y;

    size_t base = ((size_t)bh * S_ + s) * HD_;
    float v0 = src[base + i];
    float v1 = src[base + i + 64];
    float o0 = v0 * c - v1 * sn;
    float o1 = v1 * c + v0 * sn;
    if (isQ) {
        float h0 = __half2float(__float2half_rn(o0));
        float h1 = __half2float(__float2half_rn(o1));
        g_qh[base + i]      = __float2half_rn(h0);
        g_qh[base + i + 64] = __float2half_rn(h1);
        g_ql[base + i]      = __float2half_rn(o0 - h0);
        g_ql[base + i + 64] = __float2half_rn(o1 - h1);
    } else {
        g_kf[base + i]      = __float2half_rn(o0);
        g_kf[base + i + 64] = __float2half_rn(o1);
    }
}

// ---------------------------------------------------------------------------
// HMMA flash attention, fp16 2-product, DOUBLE-BUFFERED K/V (prefetch of
// ktile kt+1 overlaps compute of kt). One barrier per ktile.
// smem: QH, QL, {KF,VF} x 2 stages  (6 x 17408 = 104448 B).
// ---------------------------------------------------------------------------
#define FP 136
#define FT_B 17408
#define F_QH 0
#define F_QL FT_B
#define F_KF(s) ((2 + 2*(s)) * FT_B)
#define F_VF(s) ((3 + 2*(s)) * FT_B)
#define FA_SMEM_BYTES (6 * FT_B)

__global__ __launch_bounds__(128, 2) void flash_hmma_kernel()
{
    extern __shared__ char smem[];
    const uint32_t su = smem_to_u32(smem);
    const int tid = threadIdx.x;
    const int wid = tid >> 5, lane = tid & 31;
    const int wrow = wid * 16;

    const int qt = gridDim.x - 1 - blockIdx.x;
    const int q0 = qt * 64;
    const int bh = blockIdx.y;
    const int b = bh >> 4, h = bh & 15;
    const int kvh = h >> 2;

    const __half* Qhg = g_qh + (((size_t)b * H_  + h)   * S_ + q0) * HD_;
    const __half* Qlg = g_ql + (((size_t)b * H_  + h)   * S_ + q0) * HD_;
    const __half* Kfg = g_kf + (((size_t)b * KV_ + kvh) * S_) * HD_;
    const __half* Vfg = g_vf + (((size_t)b * KV_ + kvh) * S_) * HD_;

    const int r8 = lane & 7, grp = lane >> 3;
    const int a_r = (grp & 1) * 8 + r8;
    const int a_c = (grp >> 1) * 8;
    const int b_r = (grp >> 1) * 8 + r8;
    const int b_c = (grp & 1) * 8;
    const int v_r = (grp & 1) * 8 + r8;
    const int v_c = (grp >> 1) * 8;

    auto load_kv = [&](int kt_, int stg_) {
        const int j0_ = kt_ * 64;
        #pragma unroll
        for (int it = 0; it < 8; it++) {
            int chunk = it * 128 + tid;
            int r = chunk >> 4, c = (chunk & 15) * 8;
            uint32_t so = (uint32_t)(r * FP + c) * 2;
            const size_t go = (size_t)(j0_ + r) * HD_ + c;
            cp_async16(su + F_KF(stg_) + so, Kfg + go);
            cp_async16(su + F_VF(stg_) + so, Vfg + go);
        }
        asm volatile("cp.async.commit_group;");
    };

    // preamble group: Q (hi+lo) + KV tile 0
    #pragma unroll
    for (int it = 0; it < 8; it++) {
        int chunk = it * 128 + tid;
        int r = chunk >> 4, c = (chunk & 15) * 8;
        uint32_t so = (uint32_t)(r * FP + c) * 2;
        const size_t go = (size_t)r * HD_ + c;
        cp_async16(su + F_QH + so, Qhg + go);
        cp_async16(su + F_QL + so, Qlg + go);
    }
    load_kv(0, 0);   // commits Q + KV0 as one group

    float out[16][4];
    #pragma unroll
    for (int i = 0; i < 16; i++)
        #pragma unroll
        for (int j = 0; j < 4; j++) out[i][j] = 0.0f;
    float m0 = -1e30f, m1 = -1e30f, l0 = 0.0f, l1 = 0.0f;

    const float cexp = 0.08838834764831845f * 1.4426950408889634f;
    const int ktiles = qt + 1;

    for (int kt = 0; kt < ktiles; kt++) {
        const int stg = kt & 1;
        asm volatile("cp.async.wait_group 0;");   // data for kt ready
        __syncthreads();                          // + all done with stage stg^1
        if (kt + 1 < ktiles) load_kv(kt + 1, stg ^ 1);

        // ---- S = (Qh + Ql) @ K^T : 2 products, K regs reused ----
        float s[8][4];
        #pragma unroll
        for (int i = 0; i < 8; i++)
            #pragma unroll
            for (int j = 0; j < 4; j++) s[i][j] = 0.0f;

        #pragma unroll
        for (int ks = 0; ks < 8; ks++) {
            const int klo = ks * 16;
            uint32_t qh[4], ql[4], kf[4][4];
            uint32_t qa = (uint32_t)((wrow + a_r) * FP + klo + a_c) * 2;
            ldsm4(qh, su + F_QH + qa);
            ldsm4(ql, su + F_QL + qa);
            #pragma unroll
            for (int ng = 0; ng < 4; ng++)
                ldsm4(kf[ng], su + F_KF(stg) +
                      (uint32_t)((ng * 16 + b_r) * FP + klo + b_c) * 2);
            #pragma unroll
            for (int ng = 0; ng < 4; ng++) {
                mma16816(s[2*ng],   qh, kf[ng]);
                mma16816(s[2*ng+1], qh, kf[ng] + 2);
            }
            #pragma unroll
            for (int ng = 0; ng < 4; ng++) {
                mma16816(s[2*ng],   ql, kf[ng]);
                mma16816(s[2*ng+1], ql, kf[ng] + 2);
            }
        }

        // ---- causal mask (diagonal tile only) ----
        if (kt == ktiles - 1) {
            const int rl0 = wrow + (lane >> 2);
            const int cl  = 2 * (lane & 3);
            #pragma unroll
            for (int nt = 0; nt < 8; nt++) {
                int c0 = nt * 8 + cl;
                if (c0 > rl0)     s[nt][0] = -1e30f;
                if (c0 + 1 > rl0) s[nt][1] = -1e30f;
                if (c0 > rl0 + 8)     s[nt][2] = -1e30f;
                if (c0 + 1 > rl0 + 8) s[nt][3] = -1e30f;
            }
        }

        // ---- online softmax ----
        float rmax0 = -1e30f, rmax1 = -1e30f;
        #pragma unroll
        for (int nt = 0; nt < 8; nt++) {
            rmax0 = fmaxf(rmax0, fmaxf(s[nt][0], s[nt][1]));
            rmax1 = fmaxf(rmax1, fmaxf(s[nt][2], s[nt][3]));
        }
        #pragma unroll
        for (int o = 1; o <= 2; o <<= 1) {
            rmax0 = fmaxf(rmax0, __shfl_xor_sync(0xffffffffu, rmax0, o));
            rmax1 = fmaxf(rmax1, __shfl_xor_sync(0xffffffffu, rmax1, o));
        }
        float mn0 = fmaxf(m0, rmax0), mn1 = fmaxf(m1, rmax1);
        float alpha0 = ex2f((m0 - mn0) * cexp);
        float alpha1 = ex2f((m1 - mn1) * cexp);
        m0 = mn0; m1 = mn1;

        float rs0 = 0.0f, rs1 = 0.0f;
        #pragma unroll
        for (int nt = 0; nt < 8; nt++) {
            s[nt][0] = ex2f((s[nt][0] - mn0) * cexp);
            s[nt][1] = ex2f((s[nt][1] - mn0) * cexp);
            s[nt][2] = ex2f((s[nt][2] - mn1) * cexp);
            s[nt][3] = ex2f((s[nt][3] - mn1) * cexp);
            rs0 += s[nt][0] + s[nt][1];
            rs1 += s[nt][2] + s[nt][3];
        }
        #pragma unroll
        for (int o = 1; o <= 2; o <<= 1) {
            rs0 += __shfl_xor_sync(0xffffffffu, rs0, o);
            rs1 += __shfl_xor_sync(0xffffffffu, rs1, o);
        }
        l0 = l0 * alpha0 + rs0;
        l1 = l1 * alpha1 + rs1;
        #pragma unroll
        for (int nt = 0; nt < 16; nt++) {
            out[nt][0] *= alpha0; out[nt][1] *= alpha0;
            out[nt][2] *= alpha1; out[nt][3] *= alpha1;
        }

        // ---- O += (Ph + Pl) @ V : 2 products, V regs reused ----
        #pragma unroll
        for (int kk = 0; kk < 4; kk++) {
            uint32_t ph[4], pl[4];
            #pragma unroll
            for (int half = 0; half < 2; half++) {
                const float* sp = s[2*kk + half];
                #pragma unroll
                for (int rr = 0; rr < 2; rr++) {
                    float p0 = sp[rr*2], p1 = sp[rr*2+1];
                    float h0 = __half2float(__float2half_rn(p0));
                    float h1 = __half2float(__float2half_rn(p1));
                    ph[half*2 + rr] = pack_h2(h0, h1);
                    pl[half*2 + rr] = pack_h2(p0 - h0, p1 - h1);
                }
            }
            uint32_t vf[8][4];
            uint32_t vb = (uint32_t)((kk * 16 + v_r) * FP + v_c) * 2;
            const uint32_t VN_STRIDE = 16 * 2;
            #pragma unroll
            for (int ng = 0; ng < 8; ng++)
                ldsm4t(vf[ng], su + F_VF(stg) + vb + ng * VN_STRIDE);
            #pragma unroll
            for (int ng = 0; ng < 8; ng++) {
                mma16816(out[2*ng],   ph, vf[ng]);
                mma16816(out[2*ng+1], ph, vf[ng] + 2);
            }
            #pragma unroll
            for (int ng = 0; ng < 8; ng++) {
                mma16816(out[2*ng],   pl, vf[ng]);
                mma16816(out[2*ng+1], pl, vf[ng] + 2);
            }
        }
    }

    // ---- epilogue: normalize, split fp16 hi/lo, write (B,S,H*HD) ----
    float il0 = 1.0f / l0, il1 = 1.0f / l1;
    const int row0g = q0 + wrow + (lane >> 2);
    const int cl = 2 * (lane & 3);
    #pragma unroll
    for (int ng = 0; ng < 16; ng++) {
        int col = h * HD_ + ng * 8 + cl;
        #pragma unroll
        for (int half = 0; half < 2; half++) {
            int rowg = row0g + half * 8;
            float v0 = out[ng][half*2]     * (half ? il1 : il0);
            float v1 = out[ng][half*2 + 1] * (half ? il1 : il0);
            float h0 = __half2float(__float2half_rn(v0));
            float h1 = __half2float(__float2half_rn(v1));
            size_t o = ((size_t)b * S_ + rowg) * (H_ * HD_) + col;
            *(__half2*)&g_ah[o] = __floats2half2_rn(h0, h1);
            *(__half2*)&g_al[o] = __floats2half2_rn(v0 - h0, v1 - h1);
        }
    }
}

// ---------------------------------------------------------------------------
// Launch. Keep hmma_qkv at capture slot (index 3).
// ---------------------------------------------------------------------------
extern "C" void kernel_launch(void* const* d_in, const int* in_sizes, int n_in,
                              void* d_out, int out_size)
{
    const float* x  = (const float*)d_in[0];
    const float* wq = (const float*)d_in[1];
    const float* wk = (const float*)d_in[2];
    const float* wv = (const float*)d_in[3];
    const float* wo = (const float*)d_in[4];
    const int* pos  = (const int*)d_in[6];

    __half *xh, *xl, *wqkv, *wot, *ah, *al;
    cudaGetSymbolAddress((void**)&xh, g_xh);   cudaGetSymbolAddress((void**)&xl, g_xl);
    cudaGetSymbolAddress((void**)&wqkv, g_wqkvt);
    cudaGetSymbolAddress((void**)&wot, g_wot);
    cudaGetSymbolAddress((void**)&ah, g_ah);   cudaGetSymbolAddress((void**)&al, g_al);

    const int M = B_ * S_;
    dim3 blk256(256);

    // [0] split x -> fp16 hi/lo
    {
        int n4 = M * D_ / 4;
        split_kernel<<<(n4 + 255) / 256, blk256>>>((const float4*)x,
            (__half2*)xh, (__half2*)xl, n4);
    }
    // [1] all weight transposes in one launch (single fp16)
    transpose_all_kernel<<<dim3(64, 64, 4), dim3(32, 8)>>>(
        wq, wk, wv, wo, wqkv, wot);

    // [2] RoPE cos/sin table
    rope_table_kernel<<<(S_ * (HD_/2) + 255) / 256, blk256>>>();

    cudaFuncSetAttribute(hmma_qkv_kernel, cudaFuncAttributeMaxDynamicSharedMemorySize, MM_SMEM_BYTES);
    cudaFuncSetAttribute(hmma_oproj_kernel, cudaFuncAttributeMaxDynamicSharedMemorySize, MM_SMEM_BYTES);

    // [3] merged QKV projection  <-- capture slot
    hmma_qkv_kernel<<<dim3(NQKV/128, M/128), blk256, MM_SMEM_BYTES>>>(xh, xl, wqkv);

    // [4] RoPE: Q -> fp16 hi/lo, K -> fp16
    int npairs = B_ * H_ * S_ * (HD_ / 2) + B_ * KV_ * S_ * (HD_ / 2);
    rope_split_kernel<<<(npairs + 255) / 256, blk256>>>(pos);

    // [5] flash attention
    cudaFuncSetAttribute(flash_hmma_kernel, cudaFuncAttributeMaxDynamicSharedMemorySize, FA_SMEM_BYTES);
    flash_hmma_kernel<<<dim3(S_ / 64, B_ * H_), 128, FA_SMEM_BYTES>>>();

    // [6] output projection straight into d_out
    hmma_oproj_kernel<<<dim3(D_/128, M/128), blk256, MM_SMEM_BYTES>>>(
        ah, al, wot, (float*)d_out);
}

// round 12
// speedup vs baseline: 1.0090x; 1.0090x over previous
#include <cuda_runtime.h>
#include <cuda_fp16.h>
#include <math.h>
#include <cstdint>

#define B_  2
#define S_  2048
#define D_  2048
#define H_  16
#define KV_ 4
#define HD_ 128
#define NQKV 3072   // 2048 q + 512 k + 512 v

// ---------------------------------------------------------------------------
// Helpers (base-target instructions only: ldmatrix / mma.sync / cp.async)
// ---------------------------------------------------------------------------
__device__ __forceinline__ uint32_t smem_to_u32(const void* smem_ptr) {
    uint32_t addr;
    asm("{ .reg .u64 tmp; cvta.to.shared.u64 tmp, %1; cvt.u32.u64 %0, tmp; }"
        : "=r"(addr) : "l"(smem_ptr));
    return addr;
}
__device__ __forceinline__ void cp_async16(uint32_t s, const void* g) {
    asm volatile("cp.async.cg.shared.global [%0], [%1], 16;" :: "r"(s), "l"(g));
}
__device__ __forceinline__ void ldsm4(uint32_t* r, uint32_t addr) {
    asm volatile("ldmatrix.sync.aligned.m8n8.x4.shared.b16 {%0,%1,%2,%3}, [%4];"
        : "=r"(r[0]), "=r"(r[1]), "=r"(r[2]), "=r"(r[3]) : "r"(addr));
}
__device__ __forceinline__ void ldsm4t(uint32_t* r, uint32_t addr) {
    asm volatile("ldmatrix.sync.aligned.m8n8.x4.trans.shared.b16 {%0,%1,%2,%3}, [%4];"
        : "=r"(r[0]), "=r"(r[1]), "=r"(r[2]), "=r"(r[3]) : "r"(addr));
}
// fp16 MMA, fp32 accumulate
__device__ __forceinline__ void mma16816(float* d, const uint32_t* a, const uint32_t* b) {
    asm volatile(
        "mma.sync.aligned.m16n8k16.row.col.f32.f16.f16.f32 "
        "{%0,%1,%2,%3}, {%4,%5,%6,%7}, {%8,%9}, {%0,%1,%2,%3};"
        : "+f"(d[0]), "+f"(d[1]), "+f"(d[2]), "+f"(d[3])
        : "r"(a[0]), "r"(a[1]), "r"(a[2]), "r"(a[3]), "r"(b[0]), "r"(b[1]));
}
__device__ __forceinline__ uint32_t pack_h2(float lo, float hi) {
    __half2 t = __floats2half2_rn(lo, hi);
    return *(uint32_t*)&t;
}
__device__ __forceinline__ float ex2f(float x) {
    float r; asm("ex2.approx.f32 %0, %1;" : "=f"(r) : "f"(x)); return r;
}

// ---------------------------------------------------------------------------
// Scratch (allocation-free rule: device globals)
// ---------------------------------------------------------------------------
__device__ __half g_xh[B_*S_*D_], g_xl[B_*S_*D_];
__device__ __half g_wqkvt[NQKV*D_];
__device__ __half g_wot[D_*D_];
__device__ __half g_ah[B_*S_*H_*HD_], g_al[B_*S_*H_*HD_];

__device__ __half g_qh[B_*H_*S_*HD_], g_ql[B_*H_*S_*HD_];   // roped Q split
__device__ __half g_kf[B_*KV_*S_*HD_];                      // roped K single fp16
__device__ __half g_vf[B_*KV_*S_*HD_];                      // V single fp16

__device__ float2 g_rope[S_ * (HD_/2)];

// ---------------------------------------------------------------------------
// Elementwise fp32 -> (hi, lo) fp16 split.
// ---------------------------------------------------------------------------
__global__ __launch_bounds__(256) void split_kernel(
    const float4* __restrict__ in, __half2* __restrict__ oh,
    __half2* __restrict__ ol, int n4)
{
    int i = blockIdx.x * blockDim.x + threadIdx.x;
    if (i >= n4) return;
    float4 v = in[i];
    float vs[4] = {v.x, v.y, v.z, v.w};
    float hh[4];
    #pragma unroll
    for (int j = 0; j < 4; j++) hh[j] = __half2float(__float2half_rn(vs[j]));
    oh[2*i]   = __floats2half2_rn(hh[0], hh[1]);
    oh[2*i+1] = __floats2half2_rn(hh[2], hh[3]);
    ol[2*i]   = __floats2half2_rn(vs[0] - hh[0], vs[1] - hh[1]);
    ol[2*i+1] = __floats2half2_rn(vs[2] - hh[2], vs[3] - hh[3]);
}

// ---------------------------------------------------------------------------
// Weight transposes + RoPE table, ONE launch. z=0..3: transpose regions.
// z=4: cos/sin table (fp64 phase + two-term 2pi reduction + HW sincosf).
// ---------------------------------------------------------------------------
__global__ void transpose_all_kernel(
    const float* __restrict__ wq, const float* __restrict__ wk,
    const float* __restrict__ wv, const float* __restrict__ wo,
    __half* __restrict__ qkv, __half* __restrict__ wot)
{
    const int z = blockIdx.z;
    if (z == 4) {
        int bid = blockIdx.y * gridDim.x + blockIdx.x;
        int idx = bid * 256 + threadIdx.y * 32 + threadIdx.x;
        if (idx >= S_ * (HD_/2)) return;
        int i = idx & 63, pos = idx >> 6;
        const double LOG2_THETA = 18.93156856932417108;   // log2(500000)
        double inv = exp2(-((double)i / 64.0) * LOG2_THETA);
        double f = (double)pos * inv;
        const double TWO_PI_HI = 6.283185307179586;
        const double TWO_PI_LO = 2.4492935982947064e-16;
        double n = rint(f * 0.15915494309189535);
        double r = f - n * TWO_PI_HI;
        r = r - n * TWO_PI_LO;
        float rc, rs;
        __sincosf((float)r, &rs, &rc);
        g_rope[idx] = make_float2(rc, rs);
        return;
    }
    const float* in;
    __half* oh;
    int N;
    if (z == 0)      { in = wq; oh = qkv;                     N = 2048; }
    else if (z == 1) { in = wk; oh = qkv + (size_t)2048 * D_; N = 512; }
    else if (z == 2) { in = wv; oh = qkv + (size_t)2560 * D_; N = 512; }
    else             { in = wo; oh = wot;                     N = 2048; }
    if (blockIdx.x * 32 >= N) return;

    __shared__ float tile[32][33];
    int tx = threadIdx.x, ty = threadIdx.y;
    int n0 = blockIdx.x * 32, k0 = blockIdx.y * 32;
    #pragma unroll
    for (int j = 0; j < 32; j += 8)
        tile[ty + j][tx] = in[(size_t)(k0 + ty + j) * N + n0 + tx];
    __syncthreads();
    #pragma unroll
    for (int j = 0; j < 32; j += 8) {
        float v = tile[tx][ty + j];
        oh[(size_t)(n0 + ty + j) * D_ + k0 + tx] = __float2half_rn(v);
    }
}

// ---------------------------------------------------------------------------
// GEMM mainloop: 128x128 CTA tile, 256 threads, BK=32, double-buffered
// cp.async. fp16 2-product: (Ah + Al) * Bf. B fragments reused in registers.
// (round-10 configuration — measured fastest)
// ---------------------------------------------------------------------------
#define PITCH 40
#define TILE_B (128 * PITCH * 2)
#define OFF_AH 0
#define OFF_AL TILE_B
#define OFF_BF (2 * TILE_B)
#define STAGE_SZ (3 * TILE_B)
#define MM_SMEM_BYTES (3 * STAGE_SZ)    // 92160 (stage x2 + epilogue headroom)

__device__ __forceinline__ void gemm_mainloop(
    const __half* __restrict__ Ah, const __half* __restrict__ Al,
    const __half* __restrict__ Bf,
    int K, int row0, int col0, uint32_t su, int tid, float acc[2][8][4])
{
    const int wid = tid >> 5, lane = tid & 31;
    const int warp_m = wid & 3, warp_n = wid >> 2;

    const int nchunks = K >> 5;

    auto prefetch = [&](int ck, int stg) {
        const int k0 = ck << 5;
        const uint32_t sb = su + stg * STAGE_SZ;
        #pragma unroll
        for (int h = 0; h < 2; h++) {
            int c = tid + h * 256;
            int r = c >> 2, kc = c & 3;
            uint32_t so = (uint32_t)(r * PITCH * 2 + kc * 16);
            size_t ga = (size_t)(row0 + r) * K + k0 + kc * 8;
            size_t gb = (size_t)(col0 + r) * K + k0 + kc * 8;
            cp_async16(sb + OFF_AH + so, Ah + ga);
            cp_async16(sb + OFF_AL + so, Al + ga);
            cp_async16(sb + OFF_BF + so, Bf + gb);
        }
        asm volatile("cp.async.commit_group;");
    };

    const int r8 = lane & 7, grp = lane >> 3;
    const int a_r = (grp & 1) * 8 + r8;
    const int a_c = (grp >> 1) * 8;
    const int b_r = (grp >> 1) * 8 + r8;
    const int b_c = (grp & 1) * 8;

    prefetch(0, 0);
    for (int ck = 0; ck < nchunks; ck++) {
        if (ck + 1 < nchunks) {
            prefetch(ck + 1, (ck + 1) & 1);
            asm volatile("cp.async.wait_group 1;");
        } else {
            asm volatile("cp.async.wait_group 0;");
        }
        __syncthreads();

        const uint32_t sb = su + (ck & 1) * STAGE_SZ;
        #pragma unroll
        for (int ks = 0; ks < 2; ks++) {
            const int klo = ks * 16;
            uint32_t afh[2][4], afl[2][4], bf[4][4];
            #pragma unroll
            for (int mt = 0; mt < 2; mt++) {
                uint32_t ao = ((warp_m * 32 + mt * 16 + a_r) * PITCH + klo + a_c) * 2;
                ldsm4(afh[mt], sb + OFF_AH + ao);
                ldsm4(afl[mt], sb + OFF_AL + ao);
            }
            #pragma unroll
            for (int np = 0; np < 4; np++)
                ldsm4(bf[np], sb + OFF_BF +
                      ((warp_n * 64 + np * 16 + b_r) * PITCH + klo + b_c) * 2);
            // P1: Ah * Bf
            #pragma unroll
            for (int np = 0; np < 4; np++)
                #pragma unroll
                for (int mt = 0; mt < 2; mt++) {
                    mma16816(acc[mt][2*np],   afh[mt], bf[np]);
                    mma16816(acc[mt][2*np+1], afh[mt], bf[np] + 2);
                }
            // P2: Al * Bf (B reused from registers)
            #pragma unroll
            for (int np = 0; np < 4; np++)
                #pragma unroll
                for (int mt = 0; mt < 2; mt++) {
                    mma16816(acc[mt][2*np],   afl[mt], bf[np]);
                    mma16816(acc[mt][2*np+1], afl[mt], bf[np] + 2);
                }
        }
        __syncthreads();
    }
}

// ---------------------------------------------------------------------------
// Merged QKV projection GEMM with FUSED RoPE epilogue.
// Region 0 (Q): stage fp32 tile in smem, rope, write fp16 hi/lo.
// Region 1 (K): stage, rope, write single fp16.
// Region 2 (V): direct fp16 rounding write.
// Each Q/K tile covers one head's full 128 dims, so the (d, d+64) rotation
// pair is always in-tile.
// ---------------------------------------------------------------------------
#define EP_PITCH 132

__global__ __launch_bounds__(256, 2) void hmma_qkv_kernel(
    const __half* __restrict__ Ah, const __half* __restrict__ Al,
    const __half* __restrict__ Bf, const int* __restrict__ pos_ids)
{
    extern __shared__ char smem[];
    const uint32_t su = smem_to_u32(smem);
    const int tid = threadIdx.x;
    const int wid = tid >> 5, lane = tid & 31;
    const int warp_m = wid & 3, warp_n = wid >> 2;
    const int row0 = blockIdx.y * 128, col0 = blockIdx.x * 128;

    float acc[2][8][4];
    #pragma unroll
    for (int i = 0; i < 2; i++)
        #pragma unroll
        for (int j = 0; j < 8; j++)
            #pragma unroll
            for (int k = 0; k < 4; k++) acc[i][j][k] = 0.0f;

    gemm_mainloop(Ah, Al, Bf, D_, row0, col0, su, tid, acc);

    const int r4 = lane >> 2, c2 = (lane & 3) * 2;
    const int region = (col0 < 2048) ? 0 : (col0 < 2560 ? 1 : 2);

    if (region == 2) {
        // V: direct fp16 rounding
        #pragma unroll
        for (int mt = 0; mt < 2; mt++)
            #pragma unroll
            for (int half = 0; half < 2; half++) {
                int m = row0 + warp_m * 32 + mt * 16 + half * 8 + r4;
                int bb = m >> 11;
                int s  = m & (S_ - 1);
                #pragma unroll
                for (int nt = 0; nt < 8; nt++) {
                    int n = col0 + warp_n * 64 + nt * 8 + c2;
                    int nn = n - 2560;
                    int hh = nn >> 7, d = nn & 127;
                    size_t o = (((size_t)bb * KV_ + hh) * S_ + s) * HD_ + d;
                    *(__half2*)&g_vf[o] = __floats2half2_rn(
                        acc[mt][nt][half*2], acc[mt][nt][half*2+1]);
                }
            }
        return;
    }

    // Q/K: stage fp32 tile to smem
    float* tile = (float*)smem;
    #pragma unroll
    for (int mt = 0; mt < 2; mt++)
        #pragma unroll
        for (int half = 0; half < 2; half++) {
            int r = warp_m * 32 + mt * 16 + half * 8 + r4;
            #pragma unroll
            for (int nt = 0; nt < 8; nt++) {
                int c = warp_n * 64 + nt * 8 + c2;
                tile[r * EP_PITCH + c]     = acc[mt][nt][half*2];
                tile[r * EP_PITCH + c + 1] = acc[mt][nt][half*2+1];
            }
        }
    __syncthreads();

    // RoPE + convert. 128 rows x 32 float2-pairs = 4096 work items.
    #pragma unroll
    for (int it = 0; it < 16; it++) {
        int flat = it * 256 + tid;       // 0..4095
        int r = flat >> 5;               // 0..127
        int d0 = (flat & 31) * 2;        // 0,2,..,62
        int m = row0 + r;
        int bb = m >> 11;
        int s  = m & (S_ - 1);
        int pos = pos_ids[bb * S_ + s];
        float2 cs0 = g_rope[pos * 64 + d0];
        float2 cs1 = g_rope[pos * 64 + d0 + 1];
        float v0 = tile[r * EP_PITCH + d0];
        float v1 = tile[r * EP_PITCH + d0 + 1];
        float w0 = tile[r * EP_PITCH + d0 + 64];
        float w1 = tile[r * EP_PITCH + d0 + 65];
        float o0 = v0 * cs0.x - w0 * cs0.y;   // dim d0
        float o1 = v1 * cs1.x - w1 * cs1.y;   // dim d0+1
        float p0 = w0 * cs0.x + v0 * cs0.y;   // dim d0+64
        float p1 = w1 * cs1.x + v1 * cs1.y;   // dim d0+65

        if (region == 0) {
            int hh = col0 >> 7;          // head 0..15
            size_t base = (((size_t)bb * H_ + hh) * S_ + s) * HD_;
            float h0 = __half2float(__float2half_rn(o0));
            float h1 = __half2float(__float2half_rn(o1));
            *(__half2*)&g_qh[base + d0]      = __floats2half2_rn(h0, h1);
            *(__half2*)&g_ql[base + d0]      = __floats2half2_rn(o0 - h0, o1 - h1);
            float g0 = __half2float(__float2half_rn(p0));
            float g1 = __half2float(__float2half_rn(p1));
            *(__half2*)&g_qh[base + d0 + 64] = __floats2half2_rn(g0, g1);
            *(__half2*)&g_ql[base + d0 + 64] = __floats2half2_rn(p0 - g0, p1 - g1);
        } else {
            int hh = (col0 - 2048) >> 7; // kv head 0..3
            size_t base = (((size_t)bb * KV_ + hh) * S_ + s) * HD_;
            *(__half2*)&g_kf[base + d0]      = __floats2half2_rn(o0, o1);
            *(__half2*)&g_kf[base + d0 + 64] = __floats2half2_rn(p0, p1);
        }
    }
}

// ---------------------------------------------------------------------------
// Output projection GEMM: plain row-major fp32 store into d_out.
// ---------------------------------------------------------------------------
__global__ __launch_bounds__(256, 2) void hmma_oproj_kernel(
    const __half* __restrict__ Ah, const __half* __restrict__ Al,
    const __half* __restrict__ Bf, float* __restrict__ C)
{
    extern __shared__ char smem[];
    const uint32_t su = smem_to_u32(smem);
    const int tid = threadIdx.x;
    const int wid = tid >> 5, lane = tid & 31;
    const int warp_m = wid & 3, warp_n = wid >> 2;
    const int row0 = blockIdx.y * 128, col0 = blockIdx.x * 128;

    float acc[2][8][4];
    #pragma unroll
    for (int i = 0; i < 2; i++)
        #pragma unroll
        for (int j = 0; j < 8; j++)
            #pragma unroll
            for (int k = 0; k < 4; k++) acc[i][j][k] = 0.0f;

    gemm_mainloop(Ah, Al, Bf, D_, row0, col0, su, tid, acc);

    const int r4 = lane >> 2, c2 = (lane & 3) * 2;
    #pragma unroll
    for (int mt = 0; mt < 2; mt++) {
        #pragma unroll
        for (int half = 0; half < 2; half++) {
            int m = row0 + warp_m * 32 + mt * 16 + half * 8 + r4;
            #pragma unroll
            for (int nt = 0; nt < 8; nt++) {
                int n = col0 + warp_n * 64 + nt * 8 + c2;
                float2 v;
                v.x = acc[mt][nt][half * 2 + 0];
                v.y = acc[mt][nt][half * 2 + 1];
                *(float2*)&C[(size_t)m * D_ + n] = v;
            }
        }
    }
}

// ---------------------------------------------------------------------------
// HMMA flash attention (round-10 configuration), fp16 2-product.
// K/V separate commit groups; V load overlaps QK + softmax.
// ---------------------------------------------------------------------------
#define FP 136
#define FT_B 17408
#define F_QH 0
#define F_QL (1 * FT_B)
#define F_KF (2 * FT_B)
#define F_VF (3 * FT_B)
#define FA_SMEM_BYTES (4 * FT_B)

__global__ __launch_bounds__(128, 2) void flash_hmma_kernel()
{
    extern __shared__ char smem[];
    const uint32_t su = smem_to_u32(smem);
    const int tid = threadIdx.x;
    const int wid = tid >> 5, lane = tid & 31;
    const int wrow = wid * 16;

    const int qt = gridDim.x - 1 - blockIdx.x;
    const int q0 = qt * 64;
    const int bh = blockIdx.y;
    const int b = bh >> 4, h = bh & 15;
    const int kvh = h >> 2;

    const __half* Qhg = g_qh + (((size_t)b * H_  + h)   * S_ + q0) * HD_;
    const __half* Qlg = g_ql + (((size_t)b * H_  + h)   * S_ + q0) * HD_;
    const __half* Kfg = g_kf + (((size_t)b * KV_ + kvh) * S_) * HD_;
    const __half* Vfg = g_vf + (((size_t)b * KV_ + kvh) * S_) * HD_;

    const int r8 = lane & 7, grp = lane >> 3;
    const int a_r = (grp & 1) * 8 + r8;
    const int a_c = (grp >> 1) * 8;
    const int b_r = (grp >> 1) * 8 + r8;
    const int b_c = (grp & 1) * 8;
    const int v_r = (grp & 1) * 8 + r8;
    const int v_c = (grp >> 1) * 8;

    #pragma unroll
    for (int it = 0; it < 8; it++) {
        int chunk = it * 128 + tid;
        int r = chunk >> 4, c = (chunk & 15) * 8;
        uint32_t so = (uint32_t)(r * FP + c) * 2;
        const size_t go = (size_t)r * HD_ + c;
        cp_async16(su + F_QH + so, Qhg + go);
        cp_async16(su + F_QL + so, Qlg + go);
    }
    asm volatile("cp.async.commit_group;");

    float out[16][4];
    #pragma unroll
    for (int i = 0; i < 16; i++)
        #pragma unroll
        for (int j = 0; j < 4; j++) out[i][j] = 0.0f;
    float m0 = -1e30f, m1 = -1e30f, l0 = 0.0f, l1 = 0.0f;

    const float cexp = 0.08838834764831845f * 1.4426950408889634f;
    const int ktiles = qt + 1;

    for (int kt = 0; kt < ktiles; kt++) {
        const int j0 = kt * 64;
        __syncthreads();
        #pragma unroll
        for (int it = 0; it < 8; it++) {
            int chunk = it * 128 + tid;
            int r = chunk >> 4, c = (chunk & 15) * 8;
            uint32_t so = (uint32_t)(r * FP + c) * 2;
            cp_async16(su + F_KF + so, Kfg + (size_t)(j0 + r) * HD_ + c);
        }
        asm volatile("cp.async.commit_group;");
        #pragma unroll
        for (int it = 0; it < 8; it++) {
            int chunk = it * 128 + tid;
            int r = chunk >> 4, c = (chunk & 15) * 8;
            uint32_t so = (uint32_t)(r * FP + c) * 2;
            cp_async16(su + F_VF + so, Vfg + (size_t)(j0 + r) * HD_ + c);
        }
        asm volatile("cp.async.commit_group;");
        asm volatile("cp.async.wait_group 1;");
        __syncthreads();

        // ---- S = (Qh + Ql) @ K^T : 2 products, K regs reused ----
        float s[8][4];
        #pragma unroll
        for (int i = 0; i < 8; i++)
            #pragma unroll
            for (int j = 0; j < 4; j++) s[i][j] = 0.0f;

        #pragma unroll
        for (int ks = 0; ks < 8; ks++) {
            const int klo = ks * 16;
            uint32_t qh[4], ql[4], kf[4][4];
            uint32_t qa = (uint32_t)((wrow + a_r) * FP + klo + a_c) * 2;
            ldsm4(qh, su + F_QH + qa);
            ldsm4(ql, su + F_QL + qa);
            #pragma unroll
            for (int ng = 0; ng < 4; ng++)
                ldsm4(kf[ng], su + F_KF +
                      (uint32_t)((ng * 16 + b_r) * FP + klo + b_c) * 2);
            #pragma unroll
            for (int ng = 0; ng < 4; ng++) {
                mma16816(s[2*ng],   qh, kf[ng]);
                mma16816(s[2*ng+1], qh, kf[ng] + 2);
            }
            #pragma unroll
            for (int ng = 0; ng < 4; ng++) {
                mma16816(s[2*ng],   ql, kf[ng]);
                mma16816(s[2*ng+1], ql, kf[ng] + 2);
            }
        }

        // ---- causal mask (diagonal tile only) ----
        if (kt == ktiles - 1) {
            const int rl0 = wrow + (lane >> 2);
            const int cl  = 2 * (lane & 3);
            #pragma unroll
            for (int nt = 0; nt < 8; nt++) {
                int c0 = nt * 8 + cl;
                if (c0 > rl0)     s[nt][0] = -1e30f;
                if (c0 + 1 > rl0) s[nt][1] = -1e30f;
                if (c0 > rl0 + 8)     s[nt][2] = -1e30f;
                if (c0 + 1 > rl0 + 8) s[nt][3] = -1e30f;
            }
        }

        // ---- online softmax ----
        float rmax0 = -1e30f, rmax1 = -1e30f;
        #pragma unroll
        for (int nt = 0; nt < 8; nt++) {
            rmax0 = fmaxf(rmax0, fmaxf(s[nt][0], s[nt][1]));
            rmax1 = fmaxf(rmax1, fmaxf(s[nt][2], s[nt][3]));
        }
        #pragma unroll
        for (int o = 1; o <= 2; o <<= 1) {
            rmax0 = fmaxf(rmax0, __shfl_xor_sync(0xffffffffu, rmax0, o));
            rmax1 = fmaxf(rmax1, __shfl_xor_sync(0xffffffffu, rmax1, o));
        }
        float mn0 = fmaxf(m0, rmax0), mn1 = fmaxf(m1, rmax1);
        float alpha0 = ex2f((m0 - mn0) * cexp);
        float alpha1 = ex2f((m1 - mn1) * cexp);
        m0 = mn0; m1 = mn1;

        float rs0 = 0.0f, rs1 = 0.0f;
        #pragma unroll
        for (int nt = 0; nt < 8; nt++) {
            s[nt][0] = ex2f((s[nt][0] - mn0) * cexp);
            s[nt][1] = ex2f((s[nt][1] - mn0) * cexp);
            s[nt][2] = ex2f((s[nt][2] - mn1) * cexp);
            s[nt][3] = ex2f((s[nt][3] - mn1) * cexp);
            rs0 += s[nt][0] + s[nt][1];
            rs1 += s[nt][2] + s[nt][3];
        }
        #pragma unroll
        for (int o = 1; o <= 2; o <<= 1) {
            rs0 += __shfl_xor_sync(0xffffffffu, rs0, o);
            rs1 += __shfl_xor_sync(0xffffffffu, rs1, o);
        }
        l0 = l0 * alpha0 + rs0;
        l1 = l1 * alpha1 + rs1;
        #pragma unroll
        for (int nt = 0; nt < 16; nt++) {
            out[nt][0] *= alpha0; out[nt][1] *= alpha0;
            out[nt][2] *= alpha1; out[nt][3] *= alpha1;
        }

        // ---- wait V, then O += (Ph + Pl) @ V : 2 products, V regs reused ----
        asm volatile("cp.async.wait_group 0;");
        __syncthreads();

        #pragma unroll
        for (int kk = 0; kk < 4; kk++) {
            uint32_t ph[4], pl[4];
            #pragma unroll
            for (int half = 0; half < 2; half++) {
                const float* sp = s[2*kk + half];
                #pragma unroll
                for (int rr = 0; rr < 2; rr++) {
                    float p0 = sp[rr*2], p1 = sp[rr*2+1];
                    float h0 = __half2float(__float2half_rn(p0));
                    float h1 = __half2float(__float2half_rn(p1));
                    ph[half*2 + rr] = pack_h2(h0, h1);
                    pl[half*2 + rr] = pack_h2(p0 - h0, p1 - h1);
                }
            }
            uint32_t vf[8][4];
            uint32_t vb = (uint32_t)((kk * 16 + v_r) * FP + v_c) * 2;
            const uint32_t VN_STRIDE = 16 * 2;
            #pragma unroll
            for (int ng = 0; ng < 8; ng++)
                ldsm4t(vf[ng], su + F_VF + vb + ng * VN_STRIDE);
            #pragma unroll
            for (int ng = 0; ng < 8; ng++) {
                mma16816(out[2*ng],   ph, vf[ng]);
                mma16816(out[2*ng+1], ph, vf[ng] + 2);
            }
            #pragma unroll
            for (int ng = 0; ng < 8; ng++) {
                mma16816(out[2*ng],   pl, vf[ng]);
                mma16816(out[2*ng+1], pl, vf[ng] + 2);
            }
        }
    }

    // ---- epilogue: normalize, split fp16 hi/lo, write (B,S,H*HD) ----
    float il0 = 1.0f / l0, il1 = 1.0f / l1;
    const int row0g = q0 + wrow + (lane >> 2);
    const int cl = 2 * (lane & 3);
    #pragma unroll
    for (int ng = 0; ng < 16; ng++) {
        int col = h * HD_ + ng * 8 + cl;
        #pragma unroll
        for (int half = 0; half < 2; half++) {
            int rowg = row0g + half * 8;
            float v0 = out[ng][half*2]     * (half ? il1 : il0);
            float v1 = out[ng][half*2 + 1] * (half ? il1 : il0);
            float h0 = __half2float(__float2half_rn(v0));
            float h1 = __half2float(__float2half_rn(v1));
            size_t o = ((size_t)b * S_ + rowg) * (H_ * HD_) + col;
            *(__half2*)&g_ah[o] = __floats2half2_rn(h0, h1);
            *(__half2*)&g_al[o] = __floats2half2_rn(v0 - h0, v1 - h1);
        }
    }
}

// ---------------------------------------------------------------------------
// Launch. flash_hmma at index 3 == ncu capture slot.
// ---------------------------------------------------------------------------
extern "C" void kernel_launch(void* const* d_in, const int* in_sizes, int n_in,
                              void* d_out, int out_size)
{
    const float* x  = (const float*)d_in[0];
    const float* wq = (const float*)d_in[1];
    const float* wk = (const float*)d_in[2];
    const float* wv = (const float*)d_in[3];
    const float* wo = (const float*)d_in[4];
    const int* pos  = (const int*)d_in[6];

    __half *xh, *xl, *wqkv, *wot, *ah, *al;
    cudaGetSymbolAddress((void**)&xh, g_xh);   cudaGetSymbolAddress((void**)&xl, g_xl);
    cudaGetSymbolAddress((void**)&wqkv, g_wqkvt);
    cudaGetSymbolAddress((void**)&wot, g_wot);
    cudaGetSymbolAddress((void**)&ah, g_ah);   cudaGetSymbolAddress((void**)&al, g_al);

    const int M = B_ * S_;
    dim3 blk256(256);

    // [0] split x -> fp16 hi/lo
    {
        int n4 = M * D_ / 4;
        split_kernel<<<(n4 + 255) / 256, blk256>>>((const float4*)x,
            (__half2*)xh, (__half2*)xl, n4);
    }
    // [1] weight transposes + rope table, one launch
    transpose_all_kernel<<<dim3(64, 64, 5), dim3(32, 8)>>>(
        wq, wk, wv, wo, wqkv, wot);

    cudaFuncSetAttribute(hmma_qkv_kernel, cudaFuncAttributeMaxDynamicSharedMemorySize, MM_SMEM_BYTES);
    cudaFuncSetAttribute(hmma_oproj_kernel, cudaFuncAttributeMaxDynamicSharedMemorySize, MM_SMEM_BYTES);

    // [2] merged QKV projection with fused RoPE epilogue
    hmma_qkv_kernel<<<dim3(NQKV/128, M/128), blk256, MM_SMEM_BYTES>>>(
        xh, xl, wqkv, pos);

    // [3] flash attention  <-- capture slot
    cudaFuncSetAttribute(flash_hmma_kernel, cudaFuncAttributeMaxDynamicSharedMemorySize, FA_SMEM_BYTES);
    flash_hmma_kernel<<<dim3(S_ / 64, B_ * H_), 128, FA_SMEM_BYTES>>>();

    // [4] output projection straight into d_out
    hmma_oproj_kernel<<<dim3(D_/128, M/128), blk256, MM_SMEM_BYTES>>>(
        ah, al, wot, (float*)d_out);
}

// round 13
// speedup vs baseline: 1.1856x; 1.1750x over previous
#include <cuda_runtime.h>
#include <cuda_fp16.h>
#include <math.h>
#include <cstdint>

#define B_  2
#define S_  2048
#define D_  2048
#define H_  16
#define KV_ 4
#define HD_ 128
#define NQKV 3072   // 2048 q + 512 k + 512 v

// ---------------------------------------------------------------------------
// Helpers (base-target instructions only: ldmatrix / mma.sync / cp.async)
// ---------------------------------------------------------------------------
__device__ __forceinline__ uint32_t smem_to_u32(const void* smem_ptr) {
    uint32_t addr;
    asm("{ .reg .u64 tmp; cvta.to.shared.u64 tmp, %1; cvt.u32.u64 %0, tmp; }"
        : "=r"(addr) : "l"(smem_ptr));
    return addr;
}
__device__ __forceinline__ void cp_async16(uint32_t s, const void* g) {
    asm volatile("cp.async.cg.shared.global [%0], [%1], 16;" :: "r"(s), "l"(g));
}
__device__ __forceinline__ void ldsm4(uint32_t* r, uint32_t addr) {
    asm volatile("ldmatrix.sync.aligned.m8n8.x4.shared.b16 {%0,%1,%2,%3}, [%4];"
        : "=r"(r[0]), "=r"(r[1]), "=r"(r[2]), "=r"(r[3]) : "r"(addr));
}
__device__ __forceinline__ void ldsm4t(uint32_t* r, uint32_t addr) {
    asm volatile("ldmatrix.sync.aligned.m8n8.x4.trans.shared.b16 {%0,%1,%2,%3}, [%4];"
        : "=r"(r[0]), "=r"(r[1]), "=r"(r[2]), "=r"(r[3]) : "r"(addr));
}
// fp16 MMA, fp32 accumulate
__device__ __forceinline__ void mma16816(float* d, const uint32_t* a, const uint32_t* b) {
    asm volatile(
        "mma.sync.aligned.m16n8k16.row.col.f32.f16.f16.f32 "
        "{%0,%1,%2,%3}, {%4,%5,%6,%7}, {%8,%9}, {%0,%1,%2,%3};"
        : "+f"(d[0]), "+f"(d[1]), "+f"(d[2]), "+f"(d[3])
        : "r"(a[0]), "r"(a[1]), "r"(a[2]), "r"(a[3]), "r"(b[0]), "r"(b[1]));
}
__device__ __forceinline__ uint32_t pack_h2(float lo, float hi) {
    __half2 t = __floats2half2_rn(lo, hi);
    return *(uint32_t*)&t;
}
__device__ __forceinline__ float ex2f(float x) {
    float r; asm("ex2.approx.f32 %0, %1;" : "=f"(r) : "f"(x)); return r;
}

// ---------------------------------------------------------------------------
// Scratch (allocation-free rule: device globals)
// ---------------------------------------------------------------------------
__device__ __half g_xh[B_*S_*D_], g_xl[B_*S_*D_];
__device__ __half g_wqkvt[NQKV*D_];
__device__ __half g_wot[D_*D_];
__device__ __half g_af[B_*S_*H_*HD_];                       // attn out single fp16

__device__ __half g_qh[B_*H_*S_*HD_], g_ql[B_*H_*S_*HD_];   // roped Q split
__device__ __half g_kf[B_*KV_*S_*HD_];                      // roped K single fp16
__device__ __half g_vf[B_*KV_*S_*HD_];                      // V single fp16

__device__ float2 g_rope[S_ * (HD_/2)];

// ---------------------------------------------------------------------------
// Elementwise fp32 -> (hi, lo) fp16 split.
// ---------------------------------------------------------------------------
__global__ __launch_bounds__(256) void split_kernel(
    const float4* __restrict__ in, __half2* __restrict__ oh,
    __half2* __restrict__ ol, int n4)
{
    int i = blockIdx.x * blockDim.x + threadIdx.x;
    if (i >= n4) return;
    float4 v = in[i];
    float vs[4] = {v.x, v.y, v.z, v.w};
    float hh[4];
    #pragma unroll
    for (int j = 0; j < 4; j++) hh[j] = __half2float(__float2half_rn(vs[j]));
    oh[2*i]   = __floats2half2_rn(hh[0], hh[1]);
    oh[2*i+1] = __floats2half2_rn(hh[2], hh[3]);
    ol[2*i]   = __floats2half2_rn(vs[0] - hh[0], vs[1] - hh[1]);
    ol[2*i+1] = __floats2half2_rn(vs[2] - hh[2], vs[3] - hh[3]);
}

// ---------------------------------------------------------------------------
// Weight transposes + RoPE table, ONE launch. z=0..3: transpose regions.
// z=4: cos/sin table (fp64 phase + two-term 2pi reduction + HW sincosf).
// ---------------------------------------------------------------------------
__global__ void transpose_all_kernel(
    const float* __restrict__ wq, const float* __restrict__ wk,
    const float* __restrict__ wv, const float* __restrict__ wo,
    __half* __restrict__ qkv, __half* __restrict__ wot)
{
    const int z = blockIdx.z;
    if (z == 4) {
        int bid = blockIdx.y * gridDim.x + blockIdx.x;
        int idx = bid * 256 + threadIdx.y * 32 + threadIdx.x;
        if (idx >= S_ * (HD_/2)) return;
        int i = idx & 63, pos = idx >> 6;
        const double LOG2_THETA = 18.93156856932417108;   // log2(500000)
        double inv = exp2(-((double)i / 64.0) * LOG2_THETA);
        double f = (double)pos * inv;
        const double TWO_PI_HI = 6.283185307179586;
        const double TWO_PI_LO = 2.4492935982947064e-16;
        double n = rint(f * 0.15915494309189535);
        double r = f - n * TWO_PI_HI;
        r = r - n * TWO_PI_LO;
        float rc, rs;
        __sincosf((float)r, &rs, &rc);
        g_rope[idx] = make_float2(rc, rs);
        return;
    }
    const float* in;
    __half* oh;
    int N;
    if (z == 0)      { in = wq; oh = qkv;                     N = 2048; }
    else if (z == 1) { in = wk; oh = qkv + (size_t)2048 * D_; N = 512; }
    else if (z == 2) { in = wv; oh = qkv + (size_t)2560 * D_; N = 512; }
    else             { in = wo; oh = wot;                     N = 2048; }
    if (blockIdx.x * 32 >= N) return;

    __shared__ float tile[32][33];
    int tx = threadIdx.x, ty = threadIdx.y;
    int n0 = blockIdx.x * 32, k0 = blockIdx.y * 32;
    #pragma unroll
    for (int j = 0; j < 32; j += 8)
        tile[ty + j][tx] = in[(size_t)(k0 + ty + j) * N + n0 + tx];
    __syncthreads();
    #pragma unroll
    for (int j = 0; j < 32; j += 8) {
        float v = tile[tx][ty + j];
        oh[(size_t)(n0 + ty + j) * D_ + k0 + tx] = __float2half_rn(v);
    }
}

// ---------------------------------------------------------------------------
// 2-product GEMM mainloop (qkv): 128x128 tile, BK=32, double-buffered.
// ---------------------------------------------------------------------------
#define PITCH 40
#define TILE_B (128 * PITCH * 2)
#define OFF_AH 0
#define OFF_AL TILE_B
#define OFF_BF (2 * TILE_B)
#define STAGE_SZ (3 * TILE_B)
#define MM_SMEM_BYTES (3 * STAGE_SZ)    // 92160 (2 stages + epilogue headroom)

__device__ __forceinline__ void gemm_mainloop2(
    const __half* __restrict__ Ah, const __half* __restrict__ Al,
    const __half* __restrict__ Bf,
    int K, int row0, int col0, uint32_t su, int tid, float acc[2][8][4])
{
    const int wid = tid >> 5, lane = tid & 31;
    const int warp_m = wid & 3, warp_n = wid >> 2;
    const int nchunks = K >> 5;

    auto prefetch = [&](int ck, int stg) {
        const int k0 = ck << 5;
        const uint32_t sb = su + stg * STAGE_SZ;
        #pragma unroll
        for (int h = 0; h < 2; h++) {
            int c = tid + h * 256;
            int r = c >> 2, kc = c & 3;
            uint32_t so = (uint32_t)(r * PITCH * 2 + kc * 16);
            size_t ga = (size_t)(row0 + r) * K + k0 + kc * 8;
            size_t gb = (size_t)(col0 + r) * K + k0 + kc * 8;
            cp_async16(sb + OFF_AH + so, Ah + ga);
            cp_async16(sb + OFF_AL + so, Al + ga);
            cp_async16(sb + OFF_BF + so, Bf + gb);
        }
        asm volatile("cp.async.commit_group;");
    };

    const int r8 = lane & 7, grp = lane >> 3;
    const int a_r = (grp & 1) * 8 + r8;
    const int a_c = (grp >> 1) * 8;
    const int b_r = (grp >> 1) * 8 + r8;
    const int b_c = (grp & 1) * 8;

    prefetch(0, 0);
    for (int ck = 0; ck < nchunks; ck++) {
        if (ck + 1 < nchunks) {
            prefetch(ck + 1, (ck + 1) & 1);
            asm volatile("cp.async.wait_group 1;");
        } else {
            asm volatile("cp.async.wait_group 0;");
        }
        __syncthreads();

        const uint32_t sb = su + (ck & 1) * STAGE_SZ;
        #pragma unroll
        for (int ks = 0; ks < 2; ks++) {
            const int klo = ks * 16;
            uint32_t afh[2][4], afl[2][4], bf[4][4];
            #pragma unroll
            for (int mt = 0; mt < 2; mt++) {
                uint32_t ao = ((warp_m * 32 + mt * 16 + a_r) * PITCH + klo + a_c) * 2;
                ldsm4(afh[mt], sb + OFF_AH + ao);
                ldsm4(afl[mt], sb + OFF_AL + ao);
            }
            #pragma unroll
            for (int np = 0; np < 4; np++)
                ldsm4(bf[np], sb + OFF_BF +
                      ((warp_n * 64 + np * 16 + b_r) * PITCH + klo + b_c) * 2);
            #pragma unroll
            for (int np = 0; np < 4; np++)
                #pragma unroll
                for (int mt = 0; mt < 2; mt++) {
                    mma16816(acc[mt][2*np],   afh[mt], bf[np]);
                    mma16816(acc[mt][2*np+1], afh[mt], bf[np] + 2);
                }
            #pragma unroll
            for (int np = 0; np < 4; np++)
                #pragma unroll
                for (int mt = 0; mt < 2; mt++) {
                    mma16816(acc[mt][2*np],   afl[mt], bf[np]);
                    mma16816(acc[mt][2*np+1], afl[mt], bf[np] + 2);
                }
        }
        __syncthreads();
    }
}

// ---------------------------------------------------------------------------
// Merged QKV projection GEMM with FUSED RoPE epilogue (round-12).
// ---------------------------------------------------------------------------
#define EP_PITCH 132

__global__ __launch_bounds__(256, 2) void hmma_qkv_kernel(
    const __half* __restrict__ Ah, const __half* __restrict__ Al,
    const __half* __restrict__ Bf, const int* __restrict__ pos_ids)
{
    extern __shared__ char smem[];
    const uint32_t su = smem_to_u32(smem);
    const int tid = threadIdx.x;
    const int wid = tid >> 5, lane = tid & 31;
    const int warp_m = wid & 3, warp_n = wid >> 2;
    const int row0 = blockIdx.y * 128, col0 = blockIdx.x * 128;

    float acc[2][8][4];
    #pragma unroll
    for (int i = 0; i < 2; i++)
        #pragma unroll
        for (int j = 0; j < 8; j++)
            #pragma unroll
            for (int k = 0; k < 4; k++) acc[i][j][k] = 0.0f;

    gemm_mainloop2(Ah, Al, Bf, D_, row0, col0, su, tid, acc);

    const int r4 = lane >> 2, c2 = (lane & 3) * 2;
    const int region = (col0 < 2048) ? 0 : (col0 < 2560 ? 1 : 2);

    if (region == 2) {
        #pragma unroll
        for (int mt = 0; mt < 2; mt++)
            #pragma unroll
            for (int half = 0; half < 2; half++) {
                int m = row0 + warp_m * 32 + mt * 16 + half * 8 + r4;
                int bb = m >> 11;
                int s  = m & (S_ - 1);
                #pragma unroll
                for (int nt = 0; nt < 8; nt++) {
                    int n = col0 + warp_n * 64 + nt * 8 + c2;
                    int nn = n - 2560;
                    int hh = nn >> 7, d = nn & 127;
                    size_t o = (((size_t)bb * KV_ + hh) * S_ + s) * HD_ + d;
                    *(__half2*)&g_vf[o] = __floats2half2_rn(
                        acc[mt][nt][half*2], acc[mt][nt][half*2+1]);
                }
            }
        return;
    }

    float* tile = (float*)smem;
    #pragma unroll
    for (int mt = 0; mt < 2; mt++)
        #pragma unroll
        for (int half = 0; half < 2; half++) {
            int r = warp_m * 32 + mt * 16 + half * 8 + r4;
            #pragma unroll
            for (int nt = 0; nt < 8; nt++) {
                int c = warp_n * 64 + nt * 8 + c2;
                tile[r * EP_PITCH + c]     = acc[mt][nt][half*2];
                tile[r * EP_PITCH + c + 1] = acc[mt][nt][half*2+1];
            }
        }
    __syncthreads();

    #pragma unroll
    for (int it = 0; it < 16; it++) {
        int flat = it * 256 + tid;
        int r = flat >> 5;
        int d0 = (flat & 31) * 2;
        int m = row0 + r;
        int bb = m >> 11;
        int s  = m & (S_ - 1);
        int pos = pos_ids[bb * S_ + s];
        float2 cs0 = g_rope[pos * 64 + d0];
        float2 cs1 = g_rope[pos * 64 + d0 + 1];
        float v0 = tile[r * EP_PITCH + d0];
        float v1 = tile[r * EP_PITCH + d0 + 1];
        float w0 = tile[r * EP_PITCH + d0 + 64];
        float w1 = tile[r * EP_PITCH + d0 + 65];
        float o0 = v0 * cs0.x - w0 * cs0.y;
        float o1 = v1 * cs1.x - w1 * cs1.y;
        float p0 = w0 * cs0.x + v0 * cs0.y;
        float p1 = w1 * cs1.x + v1 * cs1.y;

        if (region == 0) {
            int hh = col0 >> 7;
            size_t base = (((size_t)bb * H_ + hh) * S_ + s) * HD_;
            float h0 = __half2float(__float2half_rn(o0));
            float h1 = __half2float(__float2half_rn(o1));
            *(__half2*)&g_qh[base + d0]      = __floats2half2_rn(h0, h1);
            *(__half2*)&g_ql[base + d0]      = __floats2half2_rn(o0 - h0, o1 - h1);
            float g0 = __half2float(__float2half_rn(p0));
            float g1 = __half2float(__float2half_rn(p1));
            *(__half2*)&g_qh[base + d0 + 64] = __floats2half2_rn(g0, g1);
            *(__half2*)&g_ql[base + d0 + 64] = __floats2half2_rn(p0 - g0, p1 - g1);
        } else {
            int hh = (col0 - 2048) >> 7;
            size_t base = (((size_t)bb * KV_ + hh) * S_ + s) * HD_;
            *(__half2*)&g_kf[base + d0]      = __floats2half2_rn(o0, o1);
            *(__half2*)&g_kf[base + d0 + 64] = __floats2half2_rn(p0, p1);
        }
    }
}

// ---------------------------------------------------------------------------
// Output projection GEMM, SINGLE-product (A single fp16 x Wo fp16).
// Own mainloop with 2-tile stages.
// ---------------------------------------------------------------------------
#define O_OFF_A 0
#define O_OFF_B TILE_B
#define O_STAGE (2 * TILE_B)
#define O_SMEM_BYTES (2 * O_STAGE)      // 40960

__global__ __launch_bounds__(256, 2) void hmma_oproj_kernel(
    const __half* __restrict__ Af, const __half* __restrict__ Bf,
    float* __restrict__ C)
{
    extern __shared__ char smem[];
    const uint32_t su = smem_to_u32(smem);
    const int tid = threadIdx.x;
    const int wid = tid >> 5, lane = tid & 31;
    const int warp_m = wid & 3, warp_n = wid >> 2;
    const int row0 = blockIdx.y * 128, col0 = blockIdx.x * 128;
    const int K = D_;

    float acc[2][8][4];
    #pragma unroll
    for (int i = 0; i < 2; i++)
        #pragma unroll
        for (int j = 0; j < 8; j++)
            #pragma unroll
            for (int k = 0; k < 4; k++) acc[i][j][k] = 0.0f;

    auto prefetch = [&](int ck, int stg) {
        const int k0 = ck << 5;
        const uint32_t sb = su + stg * O_STAGE;
        #pragma unroll
        for (int h = 0; h < 2; h++) {
            int c = tid + h * 256;
            int r = c >> 2, kc = c & 3;
            uint32_t so = (uint32_t)(r * PITCH * 2 + kc * 16);
            cp_async16(sb + O_OFF_A + so, Af + (size_t)(row0 + r) * K + k0 + kc * 8);
            cp_async16(sb + O_OFF_B + so, Bf + (size_t)(col0 + r) * K + k0 + kc * 8);
        }
        asm volatile("cp.async.commit_group;");
    };

    const int r8 = lane & 7, grp = lane >> 3;
    const int a_r = (grp & 1) * 8 + r8;
    const int a_c = (grp >> 1) * 8;
    const int b_r = (grp >> 1) * 8 + r8;
    const int b_c = (grp & 1) * 8;

    const int nchunks = K >> 5;
    prefetch(0, 0);
    for (int ck = 0; ck < nchunks; ck++) {
        if (ck + 1 < nchunks) {
            prefetch(ck + 1, (ck + 1) & 1);
            asm volatile("cp.async.wait_group 1;");
        } else {
            asm volatile("cp.async.wait_group 0;");
        }
        __syncthreads();

        const uint32_t sb = su + (ck & 1) * O_STAGE;
        #pragma unroll
        for (int ks = 0; ks < 2; ks++) {
            const int klo = ks * 16;
            uint32_t af[2][4], bf[4][4];
            #pragma unroll
            for (int mt = 0; mt < 2; mt++)
                ldsm4(af[mt], sb + O_OFF_A +
                      ((warp_m * 32 + mt * 16 + a_r) * PITCH + klo + a_c) * 2);
            #pragma unroll
            for (int np = 0; np < 4; np++)
                ldsm4(bf[np], sb + O_OFF_B +
                      ((warp_n * 64 + np * 16 + b_r) * PITCH + klo + b_c) * 2);
            #pragma unroll
            for (int np = 0; np < 4; np++)
                #pragma unroll
                for (int mt = 0; mt < 2; mt++) {
                    mma16816(acc[mt][2*np],   af[mt], bf[np]);
                    mma16816(acc[mt][2*np+1], af[mt], bf[np] + 2);
                }
        }
        __syncthreads();
    }

    const int r4 = lane >> 2, c2 = (lane & 3) * 2;
    #pragma unroll
    for (int mt = 0; mt < 2; mt++) {
        #pragma unroll
        for (int half = 0; half < 2; half++) {
            int m = row0 + warp_m * 32 + mt * 16 + half * 8 + r4;
            #pragma unroll
            for (int nt = 0; nt < 8; nt++) {
                int n = col0 + warp_n * 64 + nt * 8 + c2;
                float2 v;
                v.x = acc[mt][nt][half * 2 + 0];
                v.y = acc[mt][nt][half * 2 + 1];
                *(float2*)&C[(size_t)m * D_ + n] = v;
            }
        }
    }
}

// ---------------------------------------------------------------------------
// HMMA flash attention, fp16. QK: 2 products (Qh,Ql). PV: SINGLE product
// (P rounded to fp16). K/V separate commit groups.
// ---------------------------------------------------------------------------
#define FP 136
#define FT_B 17408
#define F_QH 0
#define F_QL (1 * FT_B)
#define F_KF (2 * FT_B)
#define F_VF (3 * FT_B)
#define FA_SMEM_BYTES (4 * FT_B)

__global__ __launch_bounds__(128, 2) void flash_hmma_kernel()
{
    extern __shared__ char smem[];
    const uint32_t su = smem_to_u32(smem);
    const int tid = threadIdx.x;
    const int wid = tid >> 5, lane = tid & 31;
    const int wrow = wid * 16;

    const int qt = gridDim.x - 1 - blockIdx.x;
    const int q0 = qt * 64;
    const int bh = blockIdx.y;
    const int b = bh >> 4, h = bh & 15;
    const int kvh = h >> 2;

    const __half* Qhg = g_qh + (((size_t)b * H_  + h)   * S_ + q0) * HD_;
    const __half* Qlg = g_ql + (((size_t)b * H_  + h)   * S_ + q0) * HD_;
    const __half* Kfg = g_kf + (((size_t)b * KV_ + kvh) * S_) * HD_;
    const __half* Vfg = g_vf + (((size_t)b * KV_ + kvh) * S_) * HD_;

    const int r8 = lane & 7, grp = lane >> 3;
    const int a_r = (grp & 1) * 8 + r8;
    const int a_c = (grp >> 1) * 8;
    const int b_r = (grp >> 1) * 8 + r8;
    const int b_c = (grp & 1) * 8;
    const int v_r = (grp & 1) * 8 + r8;
    const int v_c = (grp >> 1) * 8;

    #pragma unroll
    for (int it = 0; it < 8; it++) {
        int chunk = it * 128 + tid;
        int r = chunk >> 4, c = (chunk & 15) * 8;
        uint32_t so = (uint32_t)(r * FP + c) * 2;
        const size_t go = (size_t)r * HD_ + c;
        cp_async16(su + F_QH + so, Qhg + go);
        cp_async16(su + F_QL + so, Qlg + go);
    }
    asm volatile("cp.async.commit_group;");

    float out[16][4];
    #pragma unroll
    for (int i = 0; i < 16; i++)
        #pragma unroll
        for (int j = 0; j < 4; j++) out[i][j] = 0.0f;
    float m0 = -1e30f, m1 = -1e30f, l0 = 0.0f, l1 = 0.0f;

    const float cexp = 0.08838834764831845f * 1.4426950408889634f;
    const int ktiles = qt + 1;

    for (int kt = 0; kt < ktiles; kt++) {
        const int j0 = kt * 64;
        __syncthreads();
        #pragma unroll
        for (int it = 0; it < 8; it++) {
            int chunk = it * 128 + tid;
            int r = chunk >> 4, c = (chunk & 15) * 8;
            uint32_t so = (uint32_t)(r * FP + c) * 2;
            cp_async16(su + F_KF + so, Kfg + (size_t)(j0 + r) * HD_ + c);
        }
        asm volatile("cp.async.commit_group;");
        #pragma unroll
        for (int it = 0; it < 8; it++) {
            int chunk = it * 128 + tid;
            int r = chunk >> 4, c = (chunk & 15) * 8;
            uint32_t so = (uint32_t)(r * FP + c) * 2;
            cp_async16(su + F_VF + so, Vfg + (size_t)(j0 + r) * HD_ + c);
        }
        asm volatile("cp.async.commit_group;");
        asm volatile("cp.async.wait_group 1;");
        __syncthreads();

        // ---- S = (Qh + Ql) @ K^T : 2 products, K regs reused ----
        float s[8][4];
        #pragma unroll
        for (int i = 0; i < 8; i++)
            #pragma unroll
            for (int j = 0; j < 4; j++) s[i][j] = 0.0f;

        #pragma unroll
        for (int ks = 0; ks < 8; ks++) {
            const int klo = ks * 16;
            uint32_t qh[4], ql[4], kf[4][4];
            uint32_t qa = (uint32_t)((wrow + a_r) * FP + klo + a_c) * 2;
            ldsm4(qh, su + F_QH + qa);
            ldsm4(ql, su + F_QL + qa);
            #pragma unroll
            for (int ng = 0; ng < 4; ng++)
                ldsm4(kf[ng], su + F_KF +
                      (uint32_t)((ng * 16 + b_r) * FP + klo + b_c) * 2);
            #pragma unroll
            for (int ng = 0; ng < 4; ng++) {
                mma16816(s[2*ng],   qh, kf[ng]);
                mma16816(s[2*ng+1], qh, kf[ng] + 2);
            }
            #pragma unroll
            for (int ng = 0; ng < 4; ng++) {
                mma16816(s[2*ng],   ql, kf[ng]);
                mma16816(s[2*ng+1], ql, kf[ng] + 2);
            }
        }

        // ---- causal mask (diagonal tile only) ----
        if (kt == ktiles - 1) {
            const int rl0 = wrow + (lane >> 2);
            const int cl  = 2 * (lane & 3);
            #pragma unroll
            for (int nt = 0; nt < 8; nt++) {
                int c0 = nt * 8 + cl;
                if (c0 > rl0)     s[nt][0] = -1e30f;
                if (c0 + 1 > rl0) s[nt][1] = -1e30f;
                if (c0 > rl0 + 8)     s[nt][2] = -1e30f;
                if (c0 + 1 > rl0 + 8) s[nt][3] = -1e30f;
            }
        }

        // ---- online softmax ----
        float rmax0 = -1e30f, rmax1 = -1e30f;
        #pragma unroll
        for (int nt = 0; nt < 8; nt++) {
            rmax0 = fmaxf(rmax0, fmaxf(s[nt][0], s[nt][1]));
            rmax1 = fmaxf(rmax1, fmaxf(s[nt][2], s[nt][3]));
        }
        #pragma unroll
        for (int o = 1; o <= 2; o <<= 1) {
            rmax0 = fmaxf(rmax0, __shfl_xor_sync(0xffffffffu, rmax0, o));
            rmax1 = fmaxf(rmax1, __shfl_xor_sync(0xffffffffu, rmax1, o));
        }
        float mn0 = fmaxf(m0, rmax0), mn1 = fmaxf(m1, rmax1);
        float alpha0 = ex2f((m0 - mn0) * cexp);
        float alpha1 = ex2f((m1 - mn1) * cexp);
        m0 = mn0; m1 = mn1;

        float rs0 = 0.0f, rs1 = 0.0f;
        #pragma unroll
        for (int nt = 0; nt < 8; nt++) {
            s[nt][0] = ex2f((s[nt][0] - mn0) * cexp);
            s[nt][1] = ex2f((s[nt][1] - mn0) * cexp);
            s[nt][2] = ex2f((s[nt][2] - mn1) * cexp);
            s[nt][3] = ex2f((s[nt][3] - mn1) * cexp);
            rs0 += s[nt][0] + s[nt][1];
            rs1 += s[nt][2] + s[nt][3];
        }
        #pragma unroll
        for (int o = 1; o <= 2; o <<= 1) {
            rs0 += __shfl_xor_sync(0xffffffffu, rs0, o);
            rs1 += __shfl_xor_sync(0xffffffffu, rs1, o);
        }
        l0 = l0 * alpha0 + rs0;
        l1 = l1 * alpha1 + rs1;
        #pragma unroll
        for (int nt = 0; nt < 16; nt++) {
            out[nt][0] *= alpha0; out[nt][1] *= alpha0;
            out[nt][2] *= alpha1; out[nt][3] *= alpha1;
        }

        // ---- wait V, then O += P @ V : SINGLE product ----
        asm volatile("cp.async.wait_group 0;");
        __syncthreads();

        #pragma unroll
        for (int kk = 0; kk < 4; kk++) {
            uint32_t ph[4];
            #pragma unroll
            for (int half = 0; half < 2; half++) {
                const float* sp = s[2*kk + half];
                #pragma unroll
                for (int rr = 0; rr < 2; rr++)
                    ph[half*2 + rr] = pack_h2(sp[rr*2], sp[rr*2+1]);
            }
            uint32_t vf[8][4];
            uint32_t vb = (uint32_t)((kk * 16 + v_r) * FP + v_c) * 2;
            const uint32_t VN_STRIDE = 16 * 2;
            #pragma unroll
            for (int ng = 0; ng < 8; ng++)
                ldsm4t(vf[ng], su + F_VF + vb + ng * VN_STRIDE);
            #pragma unroll
            for (int ng = 0; ng < 8; ng++) {
                mma16816(out[2*ng],   ph, vf[ng]);
                mma16816(out[2*ng+1], ph, vf[ng] + 2);
            }
        }
    }

    // ---- epilogue: normalize, write single fp16 (B,S,H*HD) ----
    float il0 = 1.0f / l0, il1 = 1.0f / l1;
    const int row0g = q0 + wrow + (lane >> 2);
    const int cl = 2 * (lane & 3);
    #pragma unroll
    for (int ng = 0; ng < 16; ng++) {
        int col = h * HD_ + ng * 8 + cl;
        #pragma unroll
        for (int half = 0; half < 2; half++) {
            int rowg = row0g + half * 8;
            float v0 = out[ng][half*2]     * (half ? il1 : il0);
            float v1 = out[ng][half*2 + 1] * (half ? il1 : il0);
            size_t o = ((size_t)b * S_ + rowg) * (H_ * HD_) + col;
            *(__half2*)&g_af[o] = __floats2half2_rn(v0, v1);
        }
    }
}

// ---------------------------------------------------------------------------
// Launch. flash_hmma at index 3 == ncu capture slot.
// ---------------------------------------------------------------------------
extern "C" void kernel_launch(void* const* d_in, const int* in_sizes, int n_in,
                              void* d_out, int out_size)
{
    const float* x  = (const float*)d_in[0];
    const float* wq = (const float*)d_in[1];
    const float* wk = (const float*)d_in[2];
    const float* wv = (const float*)d_in[3];
    const float* wo = (const float*)d_in[4];
    const int* pos  = (const int*)d_in[6];

    __half *xh, *xl, *wqkv, *wot, *af;
    cudaGetSymbolAddress((void**)&xh, g_xh);   cudaGetSymbolAddress((void**)&xl, g_xl);
    cudaGetSymbolAddress((void**)&wqkv, g_wqkvt);
    cudaGetSymbolAddress((void**)&wot, g_wot);
    cudaGetSymbolAddress((void**)&af, g_af);

    const int M = B_ * S_;
    dim3 blk256(256);

    // [0] split x -> fp16 hi/lo
    {
        int n4 = M * D_ / 4;
        split_kernel<<<(n4 + 255) / 256, blk256>>>((const float4*)x,
            (__half2*)xh, (__half2*)xl, n4);
    }
    // [1] weight transposes + rope table, one launch
    transpose_all_kernel<<<dim3(64, 64, 5), dim3(32, 8)>>>(
        wq, wk, wv, wo, wqkv, wot);

    cudaFuncSetAttribute(hmma_qkv_kernel, cudaFuncAttributeMaxDynamicSharedMemorySize, MM_SMEM_BYTES);
    cudaFuncSetAttribute(hmma_oproj_kernel, cudaFuncAttributeMaxDynamicSharedMemorySize, O_SMEM_BYTES);

    // [2] merged QKV projection with fused RoPE epilogue
    hmma_qkv_kernel<<<dim3(NQKV/128, M/128), blk256, MM_SMEM_BYTES>>>(
        xh, xl, wqkv, pos);

    // [3] flash attention  <-- capture slot
    cudaFuncSetAttribute(flash_hmma_kernel, cudaFuncAttributeMaxDynamicSharedMemorySize, FA_SMEM_BYTES);
    flash_hmma_kernel<<<dim3(S_ / 64, B_ * H_), 128, FA_SMEM_BYTES>>>();

    // [4] output projection (single-product) straight into d_out
    hmma_oproj_kernel<<<dim3(D_/128, M/128), blk256, O_SMEM_BYTES>>>(
        af, wot, (float*)d_out);
}

// round 14
// speedup vs baseline: 1.5512x; 1.3083x over previous
#include <cuda_runtime.h>
#include <cuda_fp16.h>
#include <math.h>
#include <cstdint>

#define B_  2
#define S_  2048
#define D_  2048
#define H_  16
#define KV_ 4
#define HD_ 128
#define NQKV 3072   // 2048 q + 512 k + 512 v

// ---------------------------------------------------------------------------
// Helpers (base-target instructions only: ldmatrix / mma.sync / cp.async)
// ---------------------------------------------------------------------------
__device__ __forceinline__ uint32_t smem_to_u32(const void* smem_ptr) {
    uint32_t addr;
    asm("{ .reg .u64 tmp; cvta.to.shared.u64 tmp, %1; cvt.u32.u64 %0, tmp; }"
        : "=r"(addr) : "l"(smem_ptr));
    return addr;
}
__device__ __forceinline__ void cp_async16(uint32_t s, const void* g) {
    asm volatile("cp.async.cg.shared.global [%0], [%1], 16;" :: "r"(s), "l"(g));
}
__device__ __forceinline__ void ldsm4(uint32_t* r, uint32_t addr) {
    asm volatile("ldmatrix.sync.aligned.m8n8.x4.shared.b16 {%0,%1,%2,%3}, [%4];"
        : "=r"(r[0]), "=r"(r[1]), "=r"(r[2]), "=r"(r[3]) : "r"(addr));
}
__device__ __forceinline__ void ldsm4t(uint32_t* r, uint32_t addr) {
    asm volatile("ldmatrix.sync.aligned.m8n8.x4.trans.shared.b16 {%0,%1,%2,%3}, [%4];"
        : "=r"(r[0]), "=r"(r[1]), "=r"(r[2]), "=r"(r[3]) : "r"(addr));
}
// fp16 MMA, fp32 accumulate
__device__ __forceinline__ void mma16816(float* d, const uint32_t* a, const uint32_t* b) {
    asm volatile(
        "mma.sync.aligned.m16n8k16.row.col.f32.f16.f16.f32 "
        "{%0,%1,%2,%3}, {%4,%5,%6,%7}, {%8,%9}, {%0,%1,%2,%3};"
        : "+f"(d[0]), "+f"(d[1]), "+f"(d[2]), "+f"(d[3])
        : "r"(a[0]), "r"(a[1]), "r"(a[2]), "r"(a[3]), "r"(b[0]), "r"(b[1]));
}
__device__ __forceinline__ uint32_t pack_h2(float lo, float hi) {
    __half2 t = __floats2half2_rn(lo, hi);
    return *(uint32_t*)&t;
}
__device__ __forceinline__ float ex2f(float x) {
    float r; asm("ex2.approx.f32 %0, %1;" : "=f"(r) : "f"(x)); return r;
}

// ---------------------------------------------------------------------------
// Scratch (allocation-free rule: device globals)
// ---------------------------------------------------------------------------
__device__ __half g_xf[B_*S_*D_];                  // x single fp16
__device__ __half g_wqkvt[NQKV*D_];                // weights fp16 [3072,2048]
__device__ __half g_wot[D_*D_];                    // wo fp16 [N,K]
__device__ __half g_af[B_*S_*H_*HD_];              // attn out fp16

__device__ __half g_qf[B_*H_*S_*HD_];              // roped Q fp16
__device__ __half g_kf[B_*KV_*S_*HD_];             // roped K fp16
__device__ __half g_vf[B_*KV_*S_*HD_];             // V fp16

__device__ float2 g_rope[S_ * (HD_/2)];

// ---------------------------------------------------------------------------
// Elementwise fp32 -> fp16 convert.
// ---------------------------------------------------------------------------
__global__ __launch_bounds__(256) void convert_kernel(
    const float4* __restrict__ in, __half2* __restrict__ out, int n4)
{
    int i = blockIdx.x * blockDim.x + threadIdx.x;
    if (i >= n4) return;
    float4 v = in[i];
    out[2*i]   = __floats2half2_rn(v.x, v.y);
    out[2*i+1] = __floats2half2_rn(v.z, v.w);
}

// ---------------------------------------------------------------------------
// Weight transposes + RoPE table, ONE launch. z=0..3: transpose regions.
// z=4: cos/sin table (fp64 phase + two-term 2pi reduction + HW sincosf).
// ---------------------------------------------------------------------------
__global__ void transpose_all_kernel(
    const float* __restrict__ wq, const float* __restrict__ wk,
    const float* __restrict__ wv, const float* __restrict__ wo,
    __half* __restrict__ qkv, __half* __restrict__ wot)
{
    const int z = blockIdx.z;
    if (z == 4) {
        int bid = blockIdx.y * gridDim.x + blockIdx.x;
        int idx = bid * 256 + threadIdx.y * 32 + threadIdx.x;
        if (idx >= S_ * (HD_/2)) return;
        int i = idx & 63, pos = idx >> 6;
        const double LOG2_THETA = 18.93156856932417108;   // log2(500000)
        double inv = exp2(-((double)i / 64.0) * LOG2_THETA);
        double f = (double)pos * inv;
        const double TWO_PI_HI = 6.283185307179586;
        const double TWO_PI_LO = 2.4492935982947064e-16;
        double n = rint(f * 0.15915494309189535);
        double r = f - n * TWO_PI_HI;
        r = r - n * TWO_PI_LO;
        float rc, rs;
        __sincosf((float)r, &rs, &rc);
        g_rope[idx] = make_float2(rc, rs);
        return;
    }
    const float* in;
    __half* oh;
    int N;
    if (z == 0)      { in = wq; oh = qkv;                     N = 2048; }
    else if (z == 1) { in = wk; oh = qkv + (size_t)2048 * D_; N = 512; }
    else if (z == 2) { in = wv; oh = qkv + (size_t)2560 * D_; N = 512; }
    else             { in = wo; oh = wot;                     N = 2048; }
    if (blockIdx.x * 32 >= N) return;

    __shared__ float tile[32][33];
    int tx = threadIdx.x, ty = threadIdx.y;
    int n0 = blockIdx.x * 32, k0 = blockIdx.y * 32;
    #pragma unroll
    for (int j = 0; j < 32; j += 8)
        tile[ty + j][tx] = in[(size_t)(k0 + ty + j) * N + n0 + tx];
    __syncthreads();
    #pragma unroll
    for (int j = 0; j < 32; j += 8) {
        float v = tile[tx][ty + j];
        oh[(size_t)(n0 + ty + j) * D_ + k0 + tx] = __float2half_rn(v);
    }
}

// ---------------------------------------------------------------------------
// Single-product fp16 GEMM mainloop: 128x128 tile, 256 threads, BK=32,
// double-buffered cp.async. acc += A(MxK fp16) @ B(NxK fp16)^T.
// ---------------------------------------------------------------------------
#define PITCH 40
#define TILE_B (128 * PITCH * 2)        // 10240
#define G_OFF_A 0
#define G_OFF_B TILE_B
#define G_STAGE (2 * TILE_B)            // 20480
#define G_PIPE_BYTES (2 * G_STAGE)      // 40960
// qkv kernel needs a 128x132 fp32 staging tile for RoPE: 67584 B
#define QKV_SMEM_BYTES 69632
#define O_SMEM_BYTES   G_PIPE_BYTES

__device__ __forceinline__ void gemm_mainloop1(
    const __half* __restrict__ Af, const __half* __restrict__ Bf,
    int K, int row0, int col0, uint32_t su, int tid, float acc[2][8][4])
{
    const int wid = tid >> 5, lane = tid & 31;
    const int warp_m = wid & 3, warp_n = wid >> 2;
    const int nchunks = K >> 5;

    auto prefetch = [&](int ck, int stg) {
        const int k0 = ck << 5;
        const uint32_t sb = su + stg * G_STAGE;
        #pragma unroll
        for (int h = 0; h < 2; h++) {
            int c = tid + h * 256;
            int r = c >> 2, kc = c & 3;
            uint32_t so = (uint32_t)(r * PITCH * 2 + kc * 16);
            cp_async16(sb + G_OFF_A + so, Af + (size_t)(row0 + r) * K + k0 + kc * 8);
            cp_async16(sb + G_OFF_B + so, Bf + (size_t)(col0 + r) * K + k0 + kc * 8);
        }
        asm volatile("cp.async.commit_group;");
    };

    const int r8 = lane & 7, grp = lane >> 3;
    const int a_r = (grp & 1) * 8 + r8;
    const int a_c = (grp >> 1) * 8;
    const int b_r = (grp >> 1) * 8 + r8;
    const int b_c = (grp & 1) * 8;

    prefetch(0, 0);
    for (int ck = 0; ck < nchunks; ck++) {
        if (ck + 1 < nchunks) {
            prefetch(ck + 1, (ck + 1) & 1);
            asm volatile("cp.async.wait_group 1;");
        } else {
            asm volatile("cp.async.wait_group 0;");
        }
        __syncthreads();

        const uint32_t sb = su + (ck & 1) * G_STAGE;
        #pragma unroll
        for (int ks = 0; ks < 2; ks++) {
            const int klo = ks * 16;
            uint32_t af[2][4], bf[4][4];
            #pragma unroll
            for (int mt = 0; mt < 2; mt++)
                ldsm4(af[mt], sb + G_OFF_A +
                      ((warp_m * 32 + mt * 16 + a_r) * PITCH + klo + a_c) * 2);
            #pragma unroll
            for (int np = 0; np < 4; np++)
                ldsm4(bf[np], sb + G_OFF_B +
                      ((warp_n * 64 + np * 16 + b_r) * PITCH + klo + b_c) * 2);
            #pragma unroll
            for (int np = 0; np < 4; np++)
                #pragma unroll
                for (int mt = 0; mt < 2; mt++) {
                    mma16816(acc[mt][2*np],   af[mt], bf[np]);
                    mma16816(acc[mt][2*np+1], af[mt], bf[np] + 2);
                }
        }
        __syncthreads();
    }
}

// ---------------------------------------------------------------------------
// Merged QKV projection GEMM with FUSED RoPE epilogue (all fp16 single).
// ---------------------------------------------------------------------------
#define EP_PITCH 132

__global__ __launch_bounds__(256, 2) void hmma_qkv_kernel(
    const __half* __restrict__ Af, const __half* __restrict__ Bf,
    const int* __restrict__ pos_ids)
{
    extern __shared__ char smem[];
    const uint32_t su = smem_to_u32(smem);
    const int tid = threadIdx.x;
    const int wid = tid >> 5, lane = tid & 31;
    const int warp_m = wid & 3, warp_n = wid >> 2;
    const int row0 = blockIdx.y * 128, col0 = blockIdx.x * 128;

    float acc[2][8][4];
    #pragma unroll
    for (int i = 0; i < 2; i++)
        #pragma unroll
        for (int j = 0; j < 8; j++)
            #pragma unroll
            for (int k = 0; k < 4; k++) acc[i][j][k] = 0.0f;

    gemm_mainloop1(Af, Bf, D_, row0, col0, su, tid, acc);

    const int r4 = lane >> 2, c2 = (lane & 3) * 2;
    const int region = (col0 < 2048) ? 0 : (col0 < 2560 ? 1 : 2);

    if (region == 2) {
        // V: direct fp16 rounding
        #pragma unroll
        for (int mt = 0; mt < 2; mt++)
            #pragma unroll
            for (int half = 0; half < 2; half++) {
                int m = row0 + warp_m * 32 + mt * 16 + half * 8 + r4;
                int bb = m >> 11;
                int s  = m & (S_ - 1);
                #pragma unroll
                for (int nt = 0; nt < 8; nt++) {
                    int n = col0 + warp_n * 64 + nt * 8 + c2;
                    int nn = n - 2560;
                    int hh = nn >> 7, d = nn & 127;
                    size_t o = (((size_t)bb * KV_ + hh) * S_ + s) * HD_ + d;
                    *(__half2*)&g_vf[o] = __floats2half2_rn(
                        acc[mt][nt][half*2], acc[mt][nt][half*2+1]);
                }
            }
        return;
    }

    // Q/K: stage fp32 tile, rope, write single fp16
    float* tile = (float*)smem;
    #pragma unroll
    for (int mt = 0; mt < 2; mt++)
        #pragma unroll
        for (int half = 0; half < 2; half++) {
            int r = warp_m * 32 + mt * 16 + half * 8 + r4;
            #pragma unroll
            for (int nt = 0; nt < 8; nt++) {
                int c = warp_n * 64 + nt * 8 + c2;
                tile[r * EP_PITCH + c]     = acc[mt][nt][half*2];
                tile[r * EP_PITCH + c + 1] = acc[mt][nt][half*2+1];
            }
        }
    __syncthreads();

    #pragma unroll
    for (int it = 0; it < 16; it++) {
        int flat = it * 256 + tid;
        int r = flat >> 5;
        int d0 = (flat & 31) * 2;
        int m = row0 + r;
        int bb = m >> 11;
        int s  = m & (S_ - 1);
        int pos = pos_ids[bb * S_ + s];
        float2 cs0 = g_rope[pos * 64 + d0];
        float2 cs1 = g_rope[pos * 64 + d0 + 1];
        float v0 = tile[r * EP_PITCH + d0];
        float v1 = tile[r * EP_PITCH + d0 + 1];
        float w0 = tile[r * EP_PITCH + d0 + 64];
        float w1 = tile[r * EP_PITCH + d0 + 65];
        float o0 = v0 * cs0.x - w0 * cs0.y;
        float o1 = v1 * cs1.x - w1 * cs1.y;
        float p0 = w0 * cs0.x + v0 * cs0.y;
        float p1 = w1 * cs1.x + v1 * cs1.y;

        if (region == 0) {
            int hh = col0 >> 7;
            size_t base = (((size_t)bb * H_ + hh) * S_ + s) * HD_;
            *(__half2*)&g_qf[base + d0]      = __floats2half2_rn(o0, o1);
            *(__half2*)&g_qf[base + d0 + 64] = __floats2half2_rn(p0, p1);
        } else {
            int hh = (col0 - 2048) >> 7;
            size_t base = (((size_t)bb * KV_ + hh) * S_ + s) * HD_;
            *(__half2*)&g_kf[base + d0]      = __floats2half2_rn(o0, o1);
            *(__half2*)&g_kf[base + d0 + 64] = __floats2half2_rn(p0, p1);
        }
    }
}

// ---------------------------------------------------------------------------
// Output projection GEMM (single-product) -> fp32 d_out.
// ---------------------------------------------------------------------------
__global__ __launch_bounds__(256, 2) void hmma_oproj_kernel(
    const __half* __restrict__ Af, const __half* __restrict__ Bf,
    float* __restrict__ C)
{
    extern __shared__ char smem[];
    const uint32_t su = smem_to_u32(smem);
    const int tid = threadIdx.x;
    const int wid = tid >> 5, lane = tid & 31;
    const int warp_m = wid & 3, warp_n = wid >> 2;
    const int row0 = blockIdx.y * 128, col0 = blockIdx.x * 128;

    float acc[2][8][4];
    #pragma unroll
    for (int i = 0; i < 2; i++)
        #pragma unroll
        for (int j = 0; j < 8; j++)
            #pragma unroll
            for (int k = 0; k < 4; k++) acc[i][j][k] = 0.0f;

    gemm_mainloop1(Af, Bf, D_, row0, col0, su, tid, acc);

    const int r4 = lane >> 2, c2 = (lane & 3) * 2;
    #pragma unroll
    for (int mt = 0; mt < 2; mt++) {
        #pragma unroll
        for (int half = 0; half < 2; half++) {
            int m = row0 + warp_m * 32 + mt * 16 + half * 8 + r4;
            #pragma unroll
            for (int nt = 0; nt < 8; nt++) {
                int n = col0 + warp_n * 64 + nt * 8 + c2;
                float2 v;
                v.x = acc[mt][nt][half * 2 + 0];
                v.y = acc[mt][nt][half * 2 + 1];
                *(float2*)&C[(size_t)m * D_ + n] = v;
            }
        }
    }
}

// ---------------------------------------------------------------------------
// HMMA flash attention, all fp16 single-product (QK and PV).
// K/V separate commit groups; V load overlaps QK + softmax.
// smem: QF, KF, VF tiles (3 x 17408 = 52224 B).
// ---------------------------------------------------------------------------
#define FP 136
#define FT_B 17408
#define F_QF 0
#define F_KF (1 * FT_B)
#define F_VF (2 * FT_B)
#define FA_SMEM_BYTES (3 * FT_B)

__global__ __launch_bounds__(128, 2) void flash_hmma_kernel()
{
    extern __shared__ char smem[];
    const uint32_t su = smem_to_u32(smem);
    const int tid = threadIdx.x;
    const int wid = tid >> 5, lane = tid & 31;
    const int wrow = wid * 16;

    const int qt = gridDim.x - 1 - blockIdx.x;
    const int q0 = qt * 64;
    const int bh = blockIdx.y;
    const int b = bh >> 4, h = bh & 15;
    const int kvh = h >> 2;

    const __half* Qfg = g_qf + (((size_t)b * H_  + h)   * S_ + q0) * HD_;
    const __half* Kfg = g_kf + (((size_t)b * KV_ + kvh) * S_) * HD_;
    const __half* Vfg = g_vf + (((size_t)b * KV_ + kvh) * S_) * HD_;

    const int r8 = lane & 7, grp = lane >> 3;
    const int a_r = (grp & 1) * 8 + r8;
    const int a_c = (grp >> 1) * 8;
    const int b_r = (grp >> 1) * 8 + r8;
    const int b_c = (grp & 1) * 8;
    const int v_r = (grp & 1) * 8 + r8;
    const int v_c = (grp >> 1) * 8;

    #pragma unroll
    for (int it = 0; it < 8; it++) {
        int chunk = it * 128 + tid;
        int r = chunk >> 4, c = (chunk & 15) * 8;
        uint32_t so = (uint32_t)(r * FP + c) * 2;
        cp_async16(su + F_QF + so, Qfg + (size_t)r * HD_ + c);
    }
    asm volatile("cp.async.commit_group;");

    float out[16][4];
    #pragma unroll
    for (int i = 0; i < 16; i++)
        #pragma unroll
        for (int j = 0; j < 4; j++) out[i][j] = 0.0f;
    float m0 = -1e30f, m1 = -1e30f, l0 = 0.0f, l1 = 0.0f;

    const float cexp = 0.08838834764831845f * 1.4426950408889634f;
    const int ktiles = qt + 1;

    for (int kt = 0; kt < ktiles; kt++) {
        const int j0 = kt * 64;
        __syncthreads();
        #pragma unroll
        for (int it = 0; it < 8; it++) {
            int chunk = it * 128 + tid;
            int r = chunk >> 4, c = (chunk & 15) * 8;
            uint32_t so = (uint32_t)(r * FP + c) * 2;
            cp_async16(su + F_KF + so, Kfg + (size_t)(j0 + r) * HD_ + c);
        }
        asm volatile("cp.async.commit_group;");
        #pragma unroll
        for (int it = 0; it < 8; it++) {
            int chunk = it * 128 + tid;
            int r = chunk >> 4, c = (chunk & 15) * 8;
            uint32_t so = (uint32_t)(r * FP + c) * 2;
            cp_async16(su + F_VF + so, Vfg + (size_t)(j0 + r) * HD_ + c);
        }
        asm volatile("cp.async.commit_group;");
        asm volatile("cp.async.wait_group 1;");
        __syncthreads();

        // ---- S = Q @ K^T : single product ----
        float s[8][4];
        #pragma unroll
        for (int i = 0; i < 8; i++)
            #pragma unroll
            for (int j = 0; j < 4; j++) s[i][j] = 0.0f;

        #pragma unroll
        for (int ks = 0; ks < 8; ks++) {
            const int klo = ks * 16;
            uint32_t qf[4], kf[4][4];
            ldsm4(qf, su + F_QF + (uint32_t)((wrow + a_r) * FP + klo + a_c) * 2);
            #pragma unroll
            for (int ng = 0; ng < 4; ng++)
                ldsm4(kf[ng], su + F_KF +
                      (uint32_t)((ng * 16 + b_r) * FP + klo + b_c) * 2);
            #pragma unroll
            for (int ng = 0; ng < 4; ng++) {
                mma16816(s[2*ng],   qf, kf[ng]);
                mma16816(s[2*ng+1], qf, kf[ng] + 2);
            }
        }

        // ---- causal mask (diagonal tile only) ----
        if (kt == ktiles - 1) {
            const int rl0 = wrow + (lane >> 2);
            const int cl  = 2 * (lane & 3);
            #pragma unroll
            for (int nt = 0; nt < 8; nt++) {
                int c0 = nt * 8 + cl;
                if (c0 > rl0)     s[nt][0] = -1e30f;
                if (c0 + 1 > rl0) s[nt][1] = -1e30f;
                if (c0 > rl0 + 8)     s[nt][2] = -1e30f;
                if (c0 + 1 > rl0 + 8) s[nt][3] = -1e30f;
            }
        }

        // ---- online softmax ----
        float rmax0 = -1e30f, rmax1 = -1e30f;
        #pragma unroll
        for (int nt = 0; nt < 8; nt++) {
            rmax0 = fmaxf(rmax0, fmaxf(s[nt][0], s[nt][1]));
            rmax1 = fmaxf(rmax1, fmaxf(s[nt][2], s[nt][3]));
        }
        #pragma unroll
        for (int o = 1; o <= 2; o <<= 1) {
            rmax0 = fmaxf(rmax0, __shfl_xor_sync(0xffffffffu, rmax0, o));
            rmax1 = fmaxf(rmax1, __shfl_xor_sync(0xffffffffu, rmax1, o));
        }
        float mn0 = fmaxf(m0, rmax0), mn1 = fmaxf(m1, rmax1);
        float alpha0 = ex2f((m0 - mn0) * cexp);
        float alpha1 = ex2f((m1 - mn1) * cexp);
        m0 = mn0; m1 = mn1;

        float rs0 = 0.0f, rs1 = 0.0f;
        #pragma unroll
        for (int nt = 0; nt < 8; nt++) {
            s[nt][0] = ex2f((s[nt][0] - mn0) * cexp);
            s[nt][1] = ex2f((s[nt][1] - mn0) * cexp);
            s[nt][2] = ex2f((s[nt][2] - mn1) * cexp);
            s[nt][3] = ex2f((s[nt][3] - mn1) * cexp);
            rs0 += s[nt][0] + s[nt][1];
            rs1 += s[nt][2] + s[nt][3];
        }
        #pragma unroll
        for (int o = 1; o <= 2; o <<= 1) {
            rs0 += __shfl_xor_sync(0xffffffffu, rs0, o);
            rs1 += __shfl_xor_sync(0xffffffffu, rs1, o);
        }
        l0 = l0 * alpha0 + rs0;
        l1 = l1 * alpha1 + rs1;
        #pragma unroll
        for (int nt = 0; nt < 16; nt++) {
            out[nt][0] *= alpha0; out[nt][1] *= alpha0;
            out[nt][2] *= alpha1; out[nt][3] *= alpha1;
        }

        // ---- wait V, then O += P @ V : single product ----
        asm volatile("cp.async.wait_group 0;");
        __syncthreads();

        #pragma unroll
        for (int kk = 0; kk < 4; kk++) {
            uint32_t ph[4];
            #pragma unroll
            for (int half = 0; half < 2; half++) {
                const float* sp = s[2*kk + half];
                #pragma unroll
                for (int rr = 0; rr < 2; rr++)
                    ph[half*2 + rr] = pack_h2(sp[rr*2], sp[rr*2+1]);
            }
            uint32_t vf[8][4];
            uint32_t vb = (uint32_t)((kk * 16 + v_r) * FP + v_c) * 2;
            const uint32_t VN_STRIDE = 16 * 2;
            #pragma unroll
            for (int ng = 0; ng < 8; ng++)
                ldsm4t(vf[ng], su + F_VF + vb + ng * VN_STRIDE);
            #pragma unroll
            for (int ng = 0; ng < 8; ng++) {
                mma16816(out[2*ng],   ph, vf[ng]);
                mma16816(out[2*ng+1], ph, vf[ng] + 2);
            }
        }
    }

    // ---- epilogue: normalize, write single fp16 (B,S,H*HD) ----
    float il0 = 1.0f / l0, il1 = 1.0f / l1;
    const int row0g = q0 + wrow + (lane >> 2);
    const int cl = 2 * (lane & 3);
    #pragma unroll
    for (int ng = 0; ng < 16; ng++) {
        int col = h * HD_ + ng * 8 + cl;
        #pragma unroll
        for (int half = 0; half < 2; half++) {
            int rowg = row0g + half * 8;
            float v0 = out[ng][half*2]     * (half ? il1 : il0);
            float v1 = out[ng][half*2 + 1] * (half ? il1 : il0);
            size_t o = ((size_t)b * S_ + rowg) * (H_ * HD_) + col;
            *(__half2*)&g_af[o] = __floats2half2_rn(v0, v1);
        }
    }
}

// ---------------------------------------------------------------------------
// Launch. flash_hmma at index 3 == ncu capture slot.
// ---------------------------------------------------------------------------
extern "C" void kernel_launch(void* const* d_in, const int* in_sizes, int n_in,
                              void* d_out, int out_size)
{
    const float* x  = (const float*)d_in[0];
    const float* wq = (const float*)d_in[1];
    const float* wk = (const float*)d_in[2];
    const float* wv = (const float*)d_in[3];
    const float* wo = (const float*)d_in[4];
    const int* pos  = (const int*)d_in[6];

    __half *xf, *wqkv, *wot, *af;
    cudaGetSymbolAddress((void**)&xf, g_xf);
    cudaGetSymbolAddress((void**)&wqkv, g_wqkvt);
    cudaGetSymbolAddress((void**)&wot, g_wot);
    cudaGetSymbolAddress((void**)&af, g_af);

    const int M = B_ * S_;
    dim3 blk256(256);

    // [0] convert x -> fp16
    {
        int n4 = M * D_ / 4;
        convert_kernel<<<(n4 + 255) / 256, blk256>>>((const float4*)x,
            (__half2*)xf, n4);
    }
    // [1] weight transposes + rope table, one launch
    transpose_all_kernel<<<dim3(64, 64, 5), dim3(32, 8)>>>(
        wq, wk, wv, wo, wqkv, wot);

    cudaFuncSetAttribute(hmma_qkv_kernel, cudaFuncAttributeMaxDynamicSharedMemorySize, QKV_SMEM_BYTES);
    cudaFuncSetAttribute(hmma_oproj_kernel, cudaFuncAttributeMaxDynamicSharedMemorySize, O_SMEM_BYTES);

    // [2] merged QKV projection with fused RoPE epilogue
    hmma_qkv_kernel<<<dim3(NQKV/128, M/128), blk256, QKV_SMEM_BYTES>>>(
        xf, wqkv, pos);

    // [3] flash attention  <-- capture slot
    cudaFuncSetAttribute(flash_hmma_kernel, cudaFuncAttributeMaxDynamicSharedMemorySize, FA_SMEM_BYTES);
    flash_hmma_kernel<<<dim3(S_ / 64, B_ * H_), 128, FA_SMEM_BYTES>>>();

    // [4] output projection (single-product) straight into d_out
    hmma_oproj_kernel<<<dim3(D_/128, M/128), blk256, O_SMEM_BYTES>>>(
        af, wot, (float*)d_out);
}

// round 15
// speedup vs baseline: 1.5984x; 1.0305x over previous
#include <cuda_runtime.h>
#include <cuda_fp16.h>
#include <math.h>
#include <cstdint>

#define B_  2
#define S_  2048
#define D_  2048
#define H_  16
#define KV_ 4
#define HD_ 128
#define NQKV 3072   // 2048 q + 512 k + 512 v

// ---------------------------------------------------------------------------
// Helpers (base-target instructions only: ldmatrix / mma.sync / cp.async)
// ---------------------------------------------------------------------------
__device__ __forceinline__ uint32_t smem_to_u32(const void* smem_ptr) {
    uint32_t addr;
    asm("{ .reg .u64 tmp; cvta.to.shared.u64 tmp, %1; cvt.u32.u64 %0, tmp; }"
        : "=r"(addr) : "l"(smem_ptr));
    return addr;
}
__device__ __forceinline__ void cp_async16(uint32_t s, const void* g) {
    asm volatile("cp.async.cg.shared.global [%0], [%1], 16;" :: "r"(s), "l"(g));
}
__device__ __forceinline__ void ldsm4(uint32_t* r, uint32_t addr) {
    asm volatile("ldmatrix.sync.aligned.m8n8.x4.shared.b16 {%0,%1,%2,%3}, [%4];"
        : "=r"(r[0]), "=r"(r[1]), "=r"(r[2]), "=r"(r[3]) : "r"(addr));
}
__device__ __forceinline__ void ldsm4t(uint32_t* r, uint32_t addr) {
    asm volatile("ldmatrix.sync.aligned.m8n8.x4.trans.shared.b16 {%0,%1,%2,%3}, [%4];"
        : "=r"(r[0]), "=r"(r[1]), "=r"(r[2]), "=r"(r[3]) : "r"(addr));
}
// fp16 MMA, fp32 accumulate
__device__ __forceinline__ void mma16816(float* d, const uint32_t* a, const uint32_t* b) {
    asm volatile(
        "mma.sync.aligned.m16n8k16.row.col.f32.f16.f16.f32 "
        "{%0,%1,%2,%3}, {%4,%5,%6,%7}, {%8,%9}, {%0,%1,%2,%3};"
        : "+f"(d[0]), "+f"(d[1]), "+f"(d[2]), "+f"(d[3])
        : "r"(a[0]), "r"(a[1]), "r"(a[2]), "r"(a[3]), "r"(b[0]), "r"(b[1]));
}
__device__ __forceinline__ uint32_t pack_h2(float lo, float hi) {
    __half2 t = __floats2half2_rn(lo, hi);
    return *(uint32_t*)&t;
}
__device__ __forceinline__ float ex2f(float x) {
    float r; asm("ex2.approx.f32 %0, %1;" : "=f"(r) : "f"(x)); return r;
}

// ---------------------------------------------------------------------------
// Scratch (allocation-free rule: device globals)
// ---------------------------------------------------------------------------
__device__ __half g_xf[B_*S_*D_];                  // x single fp16
__device__ __half g_wqkvt[NQKV*D_];                // weights fp16 [3072,2048]
__device__ __half g_wot[D_*D_];                    // wo fp16 [N,K]
__device__ __half g_af[B_*S_*H_*HD_];              // attn out fp16

__device__ __half g_qf[B_*H_*S_*HD_];              // roped Q fp16
__device__ __half g_kf[B_*KV_*S_*HD_];             // roped K fp16
__device__ __half g_vf[B_*KV_*S_*HD_];             // V fp16

__device__ float2 g_rope[S_ * (HD_/2)];

// ---------------------------------------------------------------------------
// Preprocessing mega-kernel, ONE launch:
//   z=0..3: weight transposes (fp32 [K,N] -> fp16 [N,K])
//   z=4:    RoPE cos/sin table (fp64 phase, range-reduced, HW sincosf)
//   z=5:    x fp32 -> fp16 elementwise convert
// ---------------------------------------------------------------------------
__global__ void preprocess_kernel(
    const float* __restrict__ x,
    const float* __restrict__ wq, const float* __restrict__ wk,
    const float* __restrict__ wv, const float* __restrict__ wo,
    __half* __restrict__ xf, __half* __restrict__ qkv, __half* __restrict__ wot)
{
    const int z = blockIdx.z;
    const int tid = threadIdx.y * 32 + threadIdx.x;
    if (z == 4) {
        int bid = blockIdx.y * gridDim.x + blockIdx.x;
        int idx = bid * 256 + tid;
        if (idx >= S_ * (HD_/2)) return;
        int i = idx & 63, pos = idx >> 6;
        const double LOG2_THETA = 18.93156856932417108;   // log2(500000)
        double inv = exp2(-((double)i / 64.0) * LOG2_THETA);
        double f = (double)pos * inv;
        const double TWO_PI_HI = 6.283185307179586;
        const double TWO_PI_LO = 2.4492935982947064e-16;
        double n = rint(f * 0.15915494309189535);
        double r = f - n * TWO_PI_HI;
        r = r - n * TWO_PI_LO;
        float rc, rs;
        __sincosf((float)r, &rs, &rc);
        g_rope[idx] = make_float2(rc, rs);
        return;
    }
    if (z == 5) {
        // x convert: 2,097,152 float4 over 4096 blocks -> 512 per block
        int bid = blockIdx.y * gridDim.x + blockIdx.x;
        const float4* in4 = (const float4*)x;
        __half2* out2 = (__half2*)xf;
        #pragma unroll
        for (int it = 0; it < 2; it++) {
            int i = bid * 512 + it * 256 + tid;
            float4 v = in4[i];
            out2[2*i]   = __floats2half2_rn(v.x, v.y);
            out2[2*i+1] = __floats2half2_rn(v.z, v.w);
        }
        return;
    }
    const float* in;
    __half* oh;
    int N;
    if (z == 0)      { in = wq; oh = qkv;                     N = 2048; }
    else if (z == 1) { in = wk; oh = qkv + (size_t)2048 * D_; N = 512; }
    else if (z == 2) { in = wv; oh = qkv + (size_t)2560 * D_; N = 512; }
    else             { in = wo; oh = wot;                     N = 2048; }
    if (blockIdx.x * 32 >= N) return;

    __shared__ float tile[32][33];
    int tx = threadIdx.x, ty = threadIdx.y;
    int n0 = blockIdx.x * 32, k0 = blockIdx.y * 32;
    #pragma unroll
    for (int j = 0; j < 32; j += 8)
        tile[ty + j][tx] = in[(size_t)(k0 + ty + j) * N + n0 + tx];
    __syncthreads();
    #pragma unroll
    for (int j = 0; j < 32; j += 8) {
        float v = tile[tx][ty + j];
        oh[(size_t)(n0 + ty + j) * D_ + k0 + tx] = __float2half_rn(v);
    }
}

// ---------------------------------------------------------------------------
// Single-product fp16 GEMM mainloop: 128x128 tile, 256 threads, BK=32,
// double-buffered cp.async. acc += A(MxK fp16) @ B(NxK fp16)^T.
// ---------------------------------------------------------------------------
#define PITCH 40
#define TILE_B (128 * PITCH * 2)        // 10240
#define G_OFF_A 0
#define G_OFF_B TILE_B
#define G_STAGE (2 * TILE_B)            // 20480
#define G_PIPE_BYTES (2 * G_STAGE)      // 40960
#define QKV_SMEM_BYTES 69632            // includes 128x132 fp32 RoPE staging
#define O_SMEM_BYTES   G_PIPE_BYTES

__device__ __forceinline__ void gemm_mainloop1(
    const __half* __restrict__ Af, const __half* __restrict__ Bf,
    int K, int row0, int col0, uint32_t su, int tid, float acc[2][8][4])
{
    const int wid = tid >> 5, lane = tid & 31;
    const int warp_m = wid & 3, warp_n = wid >> 2;
    const int nchunks = K >> 5;

    auto prefetch = [&](int ck, int stg) {
        const int k0 = ck << 5;
        const uint32_t sb = su + stg * G_STAGE;
        #pragma unroll
        for (int h = 0; h < 2; h++) {
            int c = tid + h * 256;
            int r = c >> 2, kc = c & 3;
            uint32_t so = (uint32_t)(r * PITCH * 2 + kc * 16);
            cp_async16(sb + G_OFF_A + so, Af + (size_t)(row0 + r) * K + k0 + kc * 8);
            cp_async16(sb + G_OFF_B + so, Bf + (size_t)(col0 + r) * K + k0 + kc * 8);
        }
        asm volatile("cp.async.commit_group;");
    };

    const int r8 = lane & 7, grp = lane >> 3;
    const int a_r = (grp & 1) * 8 + r8;
    const int a_c = (grp >> 1) * 8;
    const int b_r = (grp >> 1) * 8 + r8;
    const int b_c = (grp & 1) * 8;

    prefetch(0, 0);
    for (int ck = 0; ck < nchunks; ck++) {
        if (ck + 1 < nchunks) {
            prefetch(ck + 1, (ck + 1) & 1);
            asm volatile("cp.async.wait_group 1;");
        } else {
            asm volatile("cp.async.wait_group 0;");
        }
        __syncthreads();

        const uint32_t sb = su + (ck & 1) * G_STAGE;
        #pragma unroll
        for (int ks = 0; ks < 2; ks++) {
            const int klo = ks * 16;
            uint32_t af[2][4], bf[4][4];
            #pragma unroll
            for (int mt = 0; mt < 2; mt++)
                ldsm4(af[mt], sb + G_OFF_A +
                      ((warp_m * 32 + mt * 16 + a_r) * PITCH + klo + a_c) * 2);
            #pragma unroll
            for (int np = 0; np < 4; np++)
                ldsm4(bf[np], sb + G_OFF_B +
                      ((warp_n * 64 + np * 16 + b_r) * PITCH + klo + b_c) * 2);
            #pragma unroll
            for (int np = 0; np < 4; np++)
                #pragma unroll
                for (int mt = 0; mt < 2; mt++) {
                    mma16816(acc[mt][2*np],   af[mt], bf[np]);
                    mma16816(acc[mt][2*np+1], af[mt], bf[np] + 2);
                }
        }
        __syncthreads();
    }
}

// ---------------------------------------------------------------------------
// Merged QKV projection GEMM with FUSED RoPE epilogue (all fp16 single).
// ---------------------------------------------------------------------------
#define EP_PITCH 132

__global__ __launch_bounds__(256, 2) void hmma_qkv_kernel(
    const __half* __restrict__ Af, const __half* __restrict__ Bf,
    const int* __restrict__ pos_ids)
{
    extern __shared__ char smem[];
    const uint32_t su = smem_to_u32(smem);
    const int tid = threadIdx.x;
    const int wid = tid >> 5, lane = tid & 31;
    const int warp_m = wid & 3, warp_n = wid >> 2;
    const int row0 = blockIdx.y * 128, col0 = blockIdx.x * 128;

    float acc[2][8][4];
    #pragma unroll
    for (int i = 0; i < 2; i++)
        #pragma unroll
        for (int j = 0; j < 8; j++)
            #pragma unroll
            for (int k = 0; k < 4; k++) acc[i][j][k] = 0.0f;

    gemm_mainloop1(Af, Bf, D_, row0, col0, su, tid, acc);

    const int r4 = lane >> 2, c2 = (lane & 3) * 2;
    const int region = (col0 < 2048) ? 0 : (col0 < 2560 ? 1 : 2);

    if (region == 2) {
        #pragma unroll
        for (int mt = 0; mt < 2; mt++)
            #pragma unroll
            for (int half = 0; half < 2; half++) {
                int m = row0 + warp_m * 32 + mt * 16 + half * 8 + r4;
                int bb = m >> 11;
                int s  = m & (S_ - 1);
                #pragma unroll
                for (int nt = 0; nt < 8; nt++) {
                    int n = col0 + warp_n * 64 + nt * 8 + c2;
                    int nn = n - 2560;
                    int hh = nn >> 7, d = nn & 127;
                    size_t o = (((size_t)bb * KV_ + hh) * S_ + s) * HD_ + d;
                    *(__half2*)&g_vf[o] = __floats2half2_rn(
                        acc[mt][nt][half*2], acc[mt][nt][half*2+1]);
                }
            }
        return;
    }

    float* tile = (float*)smem;
    #pragma unroll
    for (int mt = 0; mt < 2; mt++)
        #pragma unroll
        for (int half = 0; half < 2; half++) {
            int r = warp_m * 32 + mt * 16 + half * 8 + r4;
            #pragma unroll
            for (int nt = 0; nt < 8; nt++) {
                int c = warp_n * 64 + nt * 8 + c2;
                tile[r * EP_PITCH + c]     = acc[mt][nt][half*2];
                tile[r * EP_PITCH + c + 1] = acc[mt][nt][half*2+1];
            }
        }
    __syncthreads();

    #pragma unroll
    for (int it = 0; it < 16; it++) {
        int flat = it * 256 + tid;
        int r = flat >> 5;
        int d0 = (flat & 31) * 2;
        int m = row0 + r;
        int bb = m >> 11;
        int s  = m & (S_ - 1);
        int pos = pos_ids[bb * S_ + s];
        float2 cs0 = g_rope[pos * 64 + d0];
        float2 cs1 = g_rope[pos * 64 + d0 + 1];
        float v0 = tile[r * EP_PITCH + d0];
        float v1 = tile[r * EP_PITCH + d0 + 1];
        float w0 = tile[r * EP_PITCH + d0 + 64];
        float w1 = tile[r * EP_PITCH + d0 + 65];
        float o0 = v0 * cs0.x - w0 * cs0.y;
        float o1 = v1 * cs1.x - w1 * cs1.y;
        float p0 = w0 * cs0.x + v0 * cs0.y;
        float p1 = w1 * cs1.x + v1 * cs1.y;

        if (region == 0) {
            int hh = col0 >> 7;
            size_t base = (((size_t)bb * H_ + hh) * S_ + s) * HD_;
            *(__half2*)&g_qf[base + d0]      = __floats2half2_rn(o0, o1);
            *(__half2*)&g_qf[base + d0 + 64] = __floats2half2_rn(p0, p1);
        } else {
            int hh = (col0 - 2048) >> 7;
            size_t base = (((size_t)bb * KV_ + hh) * S_ + s) * HD_;
            *(__half2*)&g_kf[base + d0]      = __floats2half2_rn(o0, o1);
            *(__half2*)&g_kf[base + d0 + 64] = __floats2half2_rn(p0, p1);
        }
    }
}

// ---------------------------------------------------------------------------
// Output projection GEMM (single-product) -> fp32 d_out.
// ---------------------------------------------------------------------------
__global__ __launch_bounds__(256, 2) void hmma_oproj_kernel(
    const __half* __restrict__ Af, const __half* __restrict__ Bf,
    float* __restrict__ C)
{
    extern __shared__ char smem[];
    const uint32_t su = smem_to_u32(smem);
    const int tid = threadIdx.x;
    const int wid = tid >> 5, lane = tid & 31;
    const int warp_m = wid & 3, warp_n = wid >> 2;
    const int row0 = blockIdx.y * 128, col0 = blockIdx.x * 128;

    float acc[2][8][4];
    #pragma unroll
    for (int i = 0; i < 2; i++)
        #pragma unroll
        for (int j = 0; j < 8; j++)
            #pragma unroll
            for (int k = 0; k < 4; k++) acc[i][j][k] = 0.0f;

    gemm_mainloop1(Af, Bf, D_, row0, col0, su, tid, acc);

    const int r4 = lane >> 2, c2 = (lane & 3) * 2;
    #pragma unroll
    for (int mt = 0; mt < 2; mt++) {
        #pragma unroll
        for (int half = 0; half < 2; half++) {
            int m = row0 + warp_m * 32 + mt * 16 + half * 8 + r4;
            #pragma unroll
            for (int nt = 0; nt < 8; nt++) {
                int n = col0 + warp_n * 64 + nt * 8 + c2;
                float2 v;
                v.x = acc[mt][nt][half * 2 + 0];
                v.y = acc[mt][nt][half * 2 + 1];
                *(float2*)&C[(size_t)m * D_ + n] = v;
            }
        }
    }
}

// ---------------------------------------------------------------------------
// HMMA flash attention, all fp16 single-product. 3 CTAs/SM target (regs<=170).
// K/V separate commit groups; V load overlaps QK + softmax.
// smem: QF, KF, VF tiles (3 x 17408 = 52224 B).
// ---------------------------------------------------------------------------
#define FP 136
#define FT_B 17408
#define F_QF 0
#define F_KF (1 * FT_B)
#define F_VF (2 * FT_B)
#define FA_SMEM_BYTES (3 * FT_B)

__global__ __launch_bounds__(128, 3) void flash_hmma_kernel()
{
    extern __shared__ char smem[];
    const uint32_t su = smem_to_u32(smem);
    const int tid = threadIdx.x;
    const int wid = tid >> 5, lane = tid & 31;
    const int wrow = wid * 16;

    const int qt = gridDim.x - 1 - blockIdx.x;
    const int q0 = qt * 64;
    const int bh = blockIdx.y;
    const int b = bh >> 4, h = bh & 15;
    const int kvh = h >> 2;

    const __half* Qfg = g_qf + (((size_t)b * H_  + h)   * S_ + q0) * HD_;
    const __half* Kfg = g_kf + (((size_t)b * KV_ + kvh) * S_) * HD_;
    const __half* Vfg = g_vf + (((size_t)b * KV_ + kvh) * S_) * HD_;

    const int r8 = lane & 7, grp = lane >> 3;
    const int a_r = (grp & 1) * 8 + r8;
    const int a_c = (grp >> 1) * 8;
    const int b_r = (grp >> 1) * 8 + r8;
    const int b_c = (grp & 1) * 8;
    const int v_r = (grp & 1) * 8 + r8;
    const int v_c = (grp >> 1) * 8;

    #pragma unroll
    for (int it = 0; it < 8; it++) {
        int chunk = it * 128 + tid;
        int r = chunk >> 4, c = (chunk & 15) * 8;
        uint32_t so = (uint32_t)(r * FP + c) * 2;
        cp_async16(su + F_QF + so, Qfg + (size_t)r * HD_ + c);
    }
    asm volatile("cp.async.commit_group;");

    float out[16][4];
    #pragma unroll
    for (int i = 0; i < 16; i++)
        #pragma unroll
        for (int j = 0; j < 4; j++) out[i][j] = 0.0f;
    float m0 = -1e30f, m1 = -1e30f, l0 = 0.0f, l1 = 0.0f;

    const float cexp = 0.08838834764831845f * 1.4426950408889634f;
    const int ktiles = qt + 1;

    for (int kt = 0; kt < ktiles; kt++) {
        const int j0 = kt * 64;
        __syncthreads();
        #pragma unroll
        for (int it = 0; it < 8; it++) {
            int chunk = it * 128 + tid;
            int r = chunk >> 4, c = (chunk & 15) * 8;
            uint32_t so = (uint32_t)(r * FP + c) * 2;
            cp_async16(su + F_KF + so, Kfg + (size_t)(j0 + r) * HD_ + c);
        }
        asm volatile("cp.async.commit_group;");
        #pragma unroll
        for (int it = 0; it < 8; it++) {
            int chunk = it * 128 + tid;
            int r = chunk >> 4, c = (chunk & 15) * 8;
            uint32_t so = (uint32_t)(r * FP + c) * 2;
            cp_async16(su + F_VF + so, Vfg + (size_t)(j0 + r) * HD_ + c);
        }
        asm volatile("cp.async.commit_group;");
        asm volatile("cp.async.wait_group 1;");
        __syncthreads();

        // ---- S = Q @ K^T : single product ----
        float s[8][4];
        #pragma unroll
        for (int i = 0; i < 8; i++)
            #pragma unroll
            for (int j = 0; j < 4; j++) s[i][j] = 0.0f;

        #pragma unroll
        for (int ks = 0; ks < 8; ks++) {
            const int klo = ks * 16;
            uint32_t qf[4], kf[4][4];
            ldsm4(qf, su + F_QF + (uint32_t)((wrow + a_r) * FP + klo + a_c) * 2);
            #pragma unroll
            for (int ng = 0; ng < 4; ng++)
                ldsm4(kf[ng], su + F_KF +
                      (uint32_t)((ng * 16 + b_r) * FP + klo + b_c) * 2);
            #pragma unroll
            for (int ng = 0; ng < 4; ng++) {
                mma16816(s[2*ng],   qf, kf[ng]);
                mma16816(s[2*ng+1], qf, kf[ng] + 2);
            }
        }

        // ---- causal mask (diagonal tile only) ----
        if (kt == ktiles - 1) {
            const int rl0 = wrow + (lane >> 2);
            const int cl  = 2 * (lane & 3);
            #pragma unroll
            for (int nt = 0; nt < 8; nt++) {
                int c0 = nt * 8 + cl;
                if (c0 > rl0)     s[nt][0] = -1e30f;
                if (c0 + 1 > rl0) s[nt][1] = -1e30f;
                if (c0 > rl0 + 8)     s[nt][2] = -1e30f;
                if (c0 + 1 > rl0 + 8) s[nt][3] = -1e30f;
            }
        }

        // ---- online softmax ----
        float rmax0 = -1e30f, rmax1 = -1e30f;
        #pragma unroll
        for (int nt = 0; nt < 8; nt++) {
            rmax0 = fmaxf(rmax0, fmaxf(s[nt][0], s[nt][1]));
            rmax1 = fmaxf(rmax1, fmaxf(s[nt][2], s[nt][3]));
        }
        #pragma unroll
        for (int o = 1; o <= 2; o <<= 1) {
            rmax0 = fmaxf(rmax0, __shfl_xor_sync(0xffffffffu, rmax0, o));
            rmax1 = fmaxf(rmax1, __shfl_xor_sync(0xffffffffu, rmax1, o));
        }
        float mn0 = fmaxf(m0, rmax0), mn1 = fmaxf(m1, rmax1);
        float alpha0 = ex2f((m0 - mn0) * cexp);
        float alpha1 = ex2f((m1 - mn1) * cexp);
        m0 = mn0; m1 = mn1;

        float rs0 = 0.0f, rs1 = 0.0f;
        #pragma unroll
        for (int nt = 0; nt < 8; nt++) {
            s[nt][0] = ex2f((s[nt][0] - mn0) * cexp);
            s[nt][1] = ex2f((s[nt][1] - mn0) * cexp);
            s[nt][2] = ex2f((s[nt][2] - mn1) * cexp);
            s[nt][3] = ex2f((s[nt][3] - mn1) * cexp);
            rs0 += s[nt][0] + s[nt][1];
            rs1 += s[nt][2] + s[nt][3];
        }
        #pragma unroll
        for (int o = 1; o <= 2; o <<= 1) {
            rs0 += __shfl_xor_sync(0xffffffffu, rs0, o);
            rs1 += __shfl_xor_sync(0xffffffffu, rs1, o);
        }
        l0 = l0 * alpha0 + rs0;
        l1 = l1 * alpha1 + rs1;
        #pragma unroll
        for (int nt = 0; nt < 16; nt++) {
            out[nt][0] *= alpha0; out[nt][1] *= alpha0;
            out[nt][2] *= alpha1; out[nt][3] *= alpha1;
        }

        // ---- wait V, then O += P @ V : single product ----
        asm volatile("cp.async.wait_group 0;");
        __syncthreads();

        #pragma unroll
        for (int kk = 0; kk < 4; kk++) {
            uint32_t ph[4];
            #pragma unroll
            for (int half = 0; half < 2; half++) {
                const float* sp = s[2*kk + half];
                #pragma unroll
                for (int rr = 0; rr < 2; rr++)
                    ph[half*2 + rr] = pack_h2(sp[rr*2], sp[rr*2+1]);
            }
            uint32_t vf[8][4];
            uint32_t vb = (uint32_t)((kk * 16 + v_r) * FP + v_c) * 2;
            const uint32_t VN_STRIDE = 16 * 2;
            #pragma unroll
            for (int ng = 0; ng < 8; ng++)
                ldsm4t(vf[ng], su + F_VF + vb + ng * VN_STRIDE);
            #pragma unroll
            for (int ng = 0; ng < 8; ng++) {
                mma16816(out[2*ng],   ph, vf[ng]);
                mma16816(out[2*ng+1], ph, vf[ng] + 2);
            }
        }
    }

    // ---- epilogue: normalize, write single fp16 (B,S,H*HD) ----
    float il0 = 1.0f / l0, il1 = 1.0f / l1;
    const int row0g = q0 + wrow + (lane >> 2);
    const int cl = 2 * (lane & 3);
    #pragma unroll
    for (int ng = 0; ng < 16; ng++) {
        int col = h * HD_ + ng * 8 + cl;
        #pragma unroll
        for (int half = 0; half < 2; half++) {
            int rowg = row0g + half * 8;
            float v0 = out[ng][half*2]     * (half ? il1 : il0);
            float v1 = out[ng][half*2 + 1] * (half ? il1 : il0);
            size_t o = ((size_t)b * S_ + rowg) * (H_ * HD_) + col;
            *(__half2*)&g_af[o] = __floats2half2_rn(v0, v1);
        }
    }
}

// ---------------------------------------------------------------------------
// Launch. flash_hmma at index 2; capture slot shifts with launch count, so
// profiled kernel may be qkv or flash — both are informative.
// ---------------------------------------------------------------------------
extern "C" void kernel_launch(void* const* d_in, const int* in_sizes, int n_in,
                              void* d_out, int out_size)
{
    const float* x  = (const float*)d_in[0];
    const float* wq = (const float*)d_in[1];
    const float* wk = (const float*)d_in[2];
    const float* wv = (const float*)d_in[3];
    const float* wo = (const float*)d_in[4];
    const int* pos  = (const int*)d_in[6];

    __half *xf, *wqkv, *wot, *af;
    cudaGetSymbolAddress((void**)&xf, g_xf);
    cudaGetSymbolAddress((void**)&wqkv, g_wqkvt);
    cudaGetSymbolAddress((void**)&wot, g_wot);
    cudaGetSymbolAddress((void**)&af, g_af);

    const int M = B_ * S_;
    dim3 blk256(256);

    // [0] preprocessing: weight transposes + rope table + x convert
    preprocess_kernel<<<dim3(64, 64, 6), dim3(32, 8)>>>(
        x, wq, wk, wv, wo, xf, wqkv, wot);

    cudaFuncSetAttribute(hmma_qkv_kernel, cudaFuncAttributeMaxDynamicSharedMemorySize, QKV_SMEM_BYTES);
    cudaFuncSetAttribute(hmma_oproj_kernel, cudaFuncAttributeMaxDynamicSharedMemorySize, O_SMEM_BYTES);

    // [1] merged QKV projection with fused RoPE epilogue
    hmma_qkv_kernel<<<dim3(NQKV/128, M/128), blk256, QKV_SMEM_BYTES>>>(
        xf, wqkv, pos);

    // [2] flash attention (3 CTAs/SM occupancy target)
    cudaFuncSetAttribute(flash_hmma_kernel, cudaFuncAttributeMaxDynamicSharedMemorySize, FA_SMEM_BYTES);
    flash_hmma_kernel<<<dim3(S_ / 64, B_ * H_), 128, FA_SMEM_BYTES>>>();

    // [3] output projection (single-product) straight into d_out
    hmma_oproj_kernel<<<dim3(D_/128, M/128), blk256, O_SMEM_BYTES>>>(
        af, wot, (float*)d_out);
}

// round 16
// speedup vs baseline: 1.6201x; 1.0135x over previous
#include <cuda_runtime.h>
#include <cuda_fp16.h>
#include <math.h>
#include <cstdint>

#define B_  2
#define S_  2048
#define D_  2048
#define H_  16
#define KV_ 4
#define HD_ 128
#define NQKV 3072   // 2048 q + 512 k + 512 v

#define NSM_CTAS 296   // 2 CTAs/SM x 148 SMs

// ---------------------------------------------------------------------------
// Helpers (base-target instructions only: ldmatrix / mma.sync / cp.async)
// ---------------------------------------------------------------------------
__device__ __forceinline__ uint32_t smem_to_u32(const void* smem_ptr) {
    uint32_t addr;
    asm("{ .reg .u64 tmp; cvta.to.shared.u64 tmp, %1; cvt.u32.u64 %0, tmp; }"
        : "=r"(addr) : "l"(smem_ptr));
    return addr;
}
__device__ __forceinline__ void cp_async16(uint32_t s, const void* g) {
    asm volatile("cp.async.cg.shared.global [%0], [%1], 16;" :: "r"(s), "l"(g));
}
__device__ __forceinline__ void ldsm4(uint32_t* r, uint32_t addr) {
    asm volatile("ldmatrix.sync.aligned.m8n8.x4.shared.b16 {%0,%1,%2,%3}, [%4];"
        : "=r"(r[0]), "=r"(r[1]), "=r"(r[2]), "=r"(r[3]) : "r"(addr));
}
__device__ __forceinline__ void ldsm4t(uint32_t* r, uint32_t addr) {
    asm volatile("ldmatrix.sync.aligned.m8n8.x4.trans.shared.b16 {%0,%1,%2,%3}, [%4];"
        : "=r"(r[0]), "=r"(r[1]), "=r"(r[2]), "=r"(r[3]) : "r"(addr));
}
// fp16 MMA, fp32 accumulate
__device__ __forceinline__ void mma16816(float* d, const uint32_t* a, const uint32_t* b) {
    asm volatile(
        "mma.sync.aligned.m16n8k16.row.col.f32.f16.f16.f32 "
        "{%0,%1,%2,%3}, {%4,%5,%6,%7}, {%8,%9}, {%0,%1,%2,%3};"
        : "+f"(d[0]), "+f"(d[1]), "+f"(d[2]), "+f"(d[3])
        : "r"(a[0]), "r"(a[1]), "r"(a[2]), "r"(a[3]), "r"(b[0]), "r"(b[1]));
}
__device__ __forceinline__ uint32_t pack_h2(float lo, float hi) {
    __half2 t = __floats2half2_rn(lo, hi);
    return *(uint32_t*)&t;
}
__device__ __forceinline__ float ex2f(float x) {
    float r; asm("ex2.approx.f32 %0, %1;" : "=f"(r) : "f"(x)); return r;
}

// ---------------------------------------------------------------------------
// Scratch (allocation-free rule: device globals)
// ---------------------------------------------------------------------------
__device__ __half g_xf[B_*S_*D_];                  // x single fp16
__device__ __half g_wqkvt[NQKV*D_];                // weights fp16 [3072,2048]
__device__ __half g_wot[D_*D_];                    // wo fp16 [N,K]
__device__ __half g_af[B_*S_*H_*HD_];              // attn out fp16

__device__ __half g_qf[B_*H_*S_*HD_];              // roped Q fp16
__device__ __half g_kf[B_*KV_*S_*HD_];             // roped K fp16
__device__ __half g_vf[B_*KV_*S_*HD_];             // V fp16

__device__ float2 g_rope[S_ * (HD_/2)];

// ---------------------------------------------------------------------------
// Preprocessing mega-kernel, ONE launch:
//   z=0..3: weight transposes (fp32 [K,N] -> fp16 [N,K])
//   z=4:    RoPE cos/sin table   z=5: x fp32 -> fp16 convert
// ---------------------------------------------------------------------------
__global__ void preprocess_kernel(
    const float* __restrict__ x,
    const float* __restrict__ wq, const float* __restrict__ wk,
    const float* __restrict__ wv, const float* __restrict__ wo,
    __half* __restrict__ xf, __half* __restrict__ qkv, __half* __restrict__ wot)
{
    const int z = blockIdx.z;
    const int tid = threadIdx.y * 32 + threadIdx.x;
    if (z == 4) {
        int bid = blockIdx.y * gridDim.x + blockIdx.x;
        int idx = bid * 256 + tid;
        if (idx >= S_ * (HD_/2)) return;
        int i = idx & 63, pos = idx >> 6;
        const double LOG2_THETA = 18.93156856932417108;   // log2(500000)
        double inv = exp2(-((double)i / 64.0) * LOG2_THETA);
        double f = (double)pos * inv;
        const double TWO_PI_HI = 6.283185307179586;
        const double TWO_PI_LO = 2.4492935982947064e-16;
        double n = rint(f * 0.15915494309189535);
        double r = f - n * TWO_PI_HI;
        r = r - n * TWO_PI_LO;
        float rc, rs;
        __sincosf((float)r, &rs, &rc);
        g_rope[idx] = make_float2(rc, rs);
        return;
    }
    if (z == 5) {
        int bid = blockIdx.y * gridDim.x + blockIdx.x;
        const float4* in4 = (const float4*)x;
        __half2* out2 = (__half2*)xf;
        #pragma unroll
        for (int it = 0; it < 2; it++) {
            int i = bid * 512 + it * 256 + tid;
            float4 v = in4[i];
            out2[2*i]   = __floats2half2_rn(v.x, v.y);
            out2[2*i+1] = __floats2half2_rn(v.z, v.w);
        }
        return;
    }
    const float* in;
    __half* oh;
    int N;
    if (z == 0)      { in = wq; oh = qkv;                     N = 2048; }
    else if (z == 1) { in = wk; oh = qkv + (size_t)2048 * D_; N = 512; }
    else if (z == 2) { in = wv; oh = qkv + (size_t)2560 * D_; N = 512; }
    else             { in = wo; oh = wot;                     N = 2048; }
    if (blockIdx.x * 32 >= N) return;

    __shared__ float tile[32][33];
    int tx = threadIdx.x, ty = threadIdx.y;
    int n0 = blockIdx.x * 32, k0 = blockIdx.y * 32;
    #pragma unroll
    for (int j = 0; j < 32; j += 8)
        tile[ty + j][tx] = in[(size_t)(k0 + ty + j) * N + n0 + tx];
    __syncthreads();
    #pragma unroll
    for (int j = 0; j < 32; j += 8) {
        float v = tile[tx][ty + j];
        oh[(size_t)(n0 + ty + j) * D_ + k0 + tx] = __float2half_rn(v);
    }
}

// ---------------------------------------------------------------------------
// Single-product fp16 GEMM mainloop: 128x128 tile, 256 threads, BK=32,
// double-buffered cp.async. acc += A(MxK fp16) @ B(NxK fp16)^T.
// ---------------------------------------------------------------------------
#define PITCH 40
#define TILE_B (128 * PITCH * 2)        // 10240
#define G_OFF_A 0
#define G_OFF_B TILE_B
#define G_STAGE (2 * TILE_B)            // 20480
#define G_PIPE_BYTES (2 * G_STAGE)      // 40960
#define QKV_SMEM_BYTES 69632            // includes 128x132 fp32 RoPE staging
#define O_SMEM_BYTES   G_PIPE_BYTES

__device__ __forceinline__ void gemm_mainloop1(
    const __half* __restrict__ Af, const __half* __restrict__ Bf,
    int K, int row0, int col0, uint32_t su, int tid, float acc[2][8][4])
{
    const int wid = tid >> 5, lane = tid & 31;
    const int warp_m = wid & 3, warp_n = wid >> 2;
    const int nchunks = K >> 5;

    auto prefetch = [&](int ck, int stg) {
        const int k0 = ck << 5;
        const uint32_t sb = su + stg * G_STAGE;
        #pragma unroll
        for (int h = 0; h < 2; h++) {
            int c = tid + h * 256;
            int r = c >> 2, kc = c & 3;
            uint32_t so = (uint32_t)(r * PITCH * 2 + kc * 16);
            cp_async16(sb + G_OFF_A + so, Af + (size_t)(row0 + r) * K + k0 + kc * 8);
            cp_async16(sb + G_OFF_B + so, Bf + (size_t)(col0 + r) * K + k0 + kc * 8);
        }
        asm volatile("cp.async.commit_group;");
    };

    const int r8 = lane & 7, grp = lane >> 3;
    const int a_r = (grp & 1) * 8 + r8;
    const int a_c = (grp >> 1) * 8;
    const int b_r = (grp >> 1) * 8 + r8;
    const int b_c = (grp & 1) * 8;

    prefetch(0, 0);
    for (int ck = 0; ck < nchunks; ck++) {
        if (ck + 1 < nchunks) {
            prefetch(ck + 1, (ck + 1) & 1);
            asm volatile("cp.async.wait_group 1;");
        } else {
            asm volatile("cp.async.wait_group 0;");
        }
        __syncthreads();

        const uint32_t sb = su + (ck & 1) * G_STAGE;
        #pragma unroll
        for (int ks = 0; ks < 2; ks++) {
            const int klo = ks * 16;
            uint32_t af[2][4], bf[4][4];
            #pragma unroll
            for (int mt = 0; mt < 2; mt++)
                ldsm4(af[mt], sb + G_OFF_A +
                      ((warp_m * 32 + mt * 16 + a_r) * PITCH + klo + a_c) * 2);
            #pragma unroll
            for (int np = 0; np < 4; np++)
                ldsm4(bf[np], sb + G_OFF_B +
                      ((warp_n * 64 + np * 16 + b_r) * PITCH + klo + b_c) * 2);
            #pragma unroll
            for (int np = 0; np < 4; np++)
                #pragma unroll
                for (int mt = 0; mt < 2; mt++) {
                    mma16816(acc[mt][2*np],   af[mt], bf[np]);
                    mma16816(acc[mt][2*np+1], af[mt], bf[np] + 2);
                }
        }
        __syncthreads();
    }
}

// ---------------------------------------------------------------------------
// PERSISTENT merged QKV projection GEMM with fused RoPE epilogue.
// grid = NSM_CTAS; each CTA loops over tiles (24 x 32 of 128x128).
// ---------------------------------------------------------------------------
#define EP_PITCH 132
#define QKV_NTX 24            // NQKV/128
#define QKV_NTILES (24 * 32)  // x M/128

__global__ __launch_bounds__(256, 2) void hmma_qkv_kernel(
    const __half* __restrict__ Af, const __half* __restrict__ Bf,
    const int* __restrict__ pos_ids)
{
    extern __shared__ char smem[];
    const uint32_t su = smem_to_u32(smem);
    const int tid = threadIdx.x;
    const int wid = tid >> 5, lane = tid & 31;
    const int warp_m = wid & 3, warp_n = wid >> 2;
    const int r4 = lane >> 2, c2 = (lane & 3) * 2;

    for (int t = blockIdx.x; t < QKV_NTILES; t += gridDim.x) {
        const int row0 = (t / QKV_NTX) * 128;
        const int col0 = (t % QKV_NTX) * 128;

        float acc[2][8][4];
        #pragma unroll
        for (int i = 0; i < 2; i++)
            #pragma unroll
            for (int j = 0; j < 8; j++)
                #pragma unroll
                for (int k = 0; k < 4; k++) acc[i][j][k] = 0.0f;

        gemm_mainloop1(Af, Bf, D_, row0, col0, su, tid, acc);

        const int region = (col0 < 2048) ? 0 : (col0 < 2560 ? 1 : 2);

        if (region == 2) {
            // V: direct fp16 rounding (registers only; no smem use)
            #pragma unroll
            for (int mt = 0; mt < 2; mt++)
                #pragma unroll
                for (int half = 0; half < 2; half++) {
                    int m = row0 + warp_m * 32 + mt * 16 + half * 8 + r4;
                    int bb = m >> 11;
                    int s  = m & (S_ - 1);
                    #pragma unroll
                    for (int nt = 0; nt < 8; nt++) {
                        int n = col0 + warp_n * 64 + nt * 8 + c2;
                        int nn = n - 2560;
                        int hh = nn >> 7, d = nn & 127;
                        size_t o = (((size_t)bb * KV_ + hh) * S_ + s) * HD_ + d;
                        *(__half2*)&g_vf[o] = __floats2half2_rn(
                            acc[mt][nt][half*2], acc[mt][nt][half*2+1]);
                    }
                }
        } else {
            // Q/K: stage fp32 tile, rope, write single fp16
            float* tile = (float*)smem;
            #pragma unroll
            for (int mt = 0; mt < 2; mt++)
                #pragma unroll
                for (int half = 0; half < 2; half++) {
                    int r = warp_m * 32 + mt * 16 + half * 8 + r4;
                    #pragma unroll
                    for (int nt = 0; nt < 8; nt++) {
                        int c = warp_n * 64 + nt * 8 + c2;
                        tile[r * EP_PITCH + c]     = acc[mt][nt][half*2];
                        tile[r * EP_PITCH + c + 1] = acc[mt][nt][half*2+1];
                    }
                }
            __syncthreads();

            #pragma unroll
            for (int it = 0; it < 16; it++) {
                int flat = it * 256 + tid;
                int r = flat >> 5;
                int d0 = (flat & 31) * 2;
                int m = row0 + r;
                int bb = m >> 11;
                int s  = m & (S_ - 1);
                int pos = pos_ids[bb * S_ + s];
                float2 cs0 = g_rope[pos * 64 + d0];
                float2 cs1 = g_rope[pos * 64 + d0 + 1];
                float v0 = tile[r * EP_PITCH + d0];
                float v1 = tile[r * EP_PITCH + d0 + 1];
                float w0 = tile[r * EP_PITCH + d0 + 64];
                float w1 = tile[r * EP_PITCH + d0 + 65];
                float o0 = v0 * cs0.x - w0 * cs0.y;
                float o1 = v1 * cs1.x - w1 * cs1.y;
                float p0 = w0 * cs0.x + v0 * cs0.y;
                float p1 = w1 * cs1.x + v1 * cs1.y;

                if (region == 0) {
                    int hh = col0 >> 7;
                    size_t base = (((size_t)bb * H_ + hh) * S_ + s) * HD_;
                    *(__half2*)&g_qf[base + d0]      = __floats2half2_rn(o0, o1);
                    *(__half2*)&g_qf[base + d0 + 64] = __floats2half2_rn(p0, p1);
                } else {
                    int hh = (col0 - 2048) >> 7;
                    size_t base = (((size_t)bb * KV_ + hh) * S_ + s) * HD_;
                    *(__half2*)&g_kf[base + d0]      = __floats2half2_rn(o0, o1);
                    *(__half2*)&g_kf[base + d0 + 64] = __floats2half2_rn(p0, p1);
                }
            }
        }
        __syncthreads();   // smem (stage/tile) safe before next tile's prefetch
    }
}

// ---------------------------------------------------------------------------
// PERSISTENT output projection GEMM (single-product) -> fp32 d_out.
// grid = NSM_CTAS; tiles 16 x 32 of 128x128.
// ---------------------------------------------------------------------------
#define O_NTX 16              // D/128
#define O_NTILES (16 * 32)

__global__ __launch_bounds__(256, 2) void hmma_oproj_kernel(
    const __half* __restrict__ Af, const __half* __restrict__ Bf,
    float* __restrict__ C)
{
    extern __shared__ char smem[];
    const uint32_t su = smem_to_u32(smem);
    const int tid = threadIdx.x;
    const int wid = tid >> 5, lane = tid & 31;
    const int warp_m = wid & 3, warp_n = wid >> 2;
    const int r4 = lane >> 2, c2 = (lane & 3) * 2;

    for (int t = blockIdx.x; t < O_NTILES; t += gridDim.x) {
        const int row0 = (t / O_NTX) * 128;
        const int col0 = (t % O_NTX) * 128;

        float acc[2][8][4];
        #pragma unroll
        for (int i = 0; i < 2; i++)
            #pragma unroll
            for (int j = 0; j < 8; j++)
                #pragma unroll
                for (int k = 0; k < 4; k++) acc[i][j][k] = 0.0f;

        gemm_mainloop1(Af, Bf, D_, row0, col0, su, tid, acc);

        #pragma unroll
        for (int mt = 0; mt < 2; mt++) {
            #pragma unroll
            for (int half = 0; half < 2; half++) {
                int m = row0 + warp_m * 32 + mt * 16 + half * 8 + r4;
                #pragma unroll
                for (int nt = 0; nt < 8; nt++) {
                    int n = col0 + warp_n * 64 + nt * 8 + c2;
                    float2 v;
                    v.x = acc[mt][nt][half * 2 + 0];
                    v.y = acc[mt][nt][half * 2 + 1];
                    *(float2*)&C[(size_t)m * D_ + n] = v;
                }
            }
        }
        __syncthreads();
    }
}

// ---------------------------------------------------------------------------
// HMMA flash attention, all fp16 single-product (round-15 config, 3 CTAs/SM).
// ---------------------------------------------------------------------------
#define FP 136
#define FT_B 17408
#define F_QF 0
#define F_KF (1 * FT_B)
#define F_VF (2 * FT_B)
#define FA_SMEM_BYTES (3 * FT_B)

__global__ __launch_bounds__(128, 3) void flash_hmma_kernel()
{
    extern __shared__ char smem[];
    const uint32_t su = smem_to_u32(smem);
    const int tid = threadIdx.x;
    const int wid = tid >> 5, lane = tid & 31;
    const int wrow = wid * 16;

    const int qt = gridDim.x - 1 - blockIdx.x;
    const int q0 = qt * 64;
    const int bh = blockIdx.y;
    const int b = bh >> 4, h = bh & 15;
    const int kvh = h >> 2;

    const __half* Qfg = g_qf + (((size_t)b * H_  + h)   * S_ + q0) * HD_;
    const __half* Kfg = g_kf + (((size_t)b * KV_ + kvh) * S_) * HD_;
    const __half* Vfg = g_vf + (((size_t)b * KV_ + kvh) * S_) * HD_;

    const int r8 = lane & 7, grp = lane >> 3;
    const int a_r = (grp & 1) * 8 + r8;
    const int a_c = (grp >> 1) * 8;
    const int b_r = (grp >> 1) * 8 + r8;
    const int b_c = (grp & 1) * 8;
    const int v_r = (grp & 1) * 8 + r8;
    const int v_c = (grp >> 1) * 8;

    #pragma unroll
    for (int it = 0; it < 8; it++) {
        int chunk = it * 128 + tid;
        int r = chunk >> 4, c = (chunk & 15) * 8;
        uint32_t so = (uint32_t)(r * FP + c) * 2;
        cp_async16(su + F_QF + so, Qfg + (size_t)r * HD_ + c);
    }
    asm volatile("cp.async.commit_group;");

    float out[16][4];
    #pragma unroll
    for (int i = 0; i < 16; i++)
        #pragma unroll
        for (int j = 0; j < 4; j++) out[i][j] = 0.0f;
    float m0 = -1e30f, m1 = -1e30f, l0 = 0.0f, l1 = 0.0f;

    const float cexp = 0.08838834764831845f * 1.4426950408889634f;
    const int ktiles = qt + 1;

    for (int kt = 0; kt < ktiles; kt++) {
        const int j0 = kt * 64;
        __syncthreads();
        #pragma unroll
        for (int it = 0; it < 8; it++) {
            int chunk = it * 128 + tid;
            int r = chunk >> 4, c = (chunk & 15) * 8;
            uint32_t so = (uint32_t)(r * FP + c) * 2;
            cp_async16(su + F_KF + so, Kfg + (size_t)(j0 + r) * HD_ + c);
        }
        asm volatile("cp.async.commit_group;");
        #pragma unroll
        for (int it = 0; it < 8; it++) {
            int chunk = it * 128 + tid;
            int r = chunk >> 4, c = (chunk & 15) * 8;
            uint32_t so = (uint32_t)(r * FP + c) * 2;
            cp_async16(su + F_VF + so, Vfg + (size_t)(j0 + r) * HD_ + c);
        }
        asm volatile("cp.async.commit_group;");
        asm volatile("cp.async.wait_group 1;");
        __syncthreads();

        // ---- S = Q @ K^T : single product ----
        float s[8][4];
        #pragma unroll
        for (int i = 0; i < 8; i++)
            #pragma unroll
            for (int j = 0; j < 4; j++) s[i][j] = 0.0f;

        #pragma unroll
        for (int ks = 0; ks < 8; ks++) {
            const int klo = ks * 16;
            uint32_t qf[4], kf[4][4];
            ldsm4(qf, su + F_QF + (uint32_t)((wrow + a_r) * FP + klo + a_c) * 2);
            #pragma unroll
            for (int ng = 0; ng < 4; ng++)
                ldsm4(kf[ng], su + F_KF +
                      (uint32_t)((ng * 16 + b_r) * FP + klo + b_c) * 2);
            #pragma unroll
            for (int ng = 0; ng < 4; ng++) {
                mma16816(s[2*ng],   qf, kf[ng]);
                mma16816(s[2*ng+1], qf, kf[ng] + 2);
            }
        }

        // ---- causal mask (diagonal tile only) ----
        if (kt == ktiles - 1) {
            const int rl0 = wrow + (lane >> 2);
            const int cl  = 2 * (lane & 3);
            #pragma unroll
            for (int nt = 0; nt < 8; nt++) {
                int c0 = nt * 8 + cl;
                if (c0 > rl0)     s[nt][0] = -1e30f;
                if (c0 + 1 > rl0) s[nt][1] = -1e30f;
                if (c0 > rl0 + 8)     s[nt][2] = -1e30f;
                if (c0 + 1 > rl0 + 8) s[nt][3] = -1e30f;
            }
        }

        // ---- online softmax ----
        float rmax0 = -1e30f, rmax1 = -1e30f;
        #pragma unroll
        for (int nt = 0; nt < 8; nt++) {
            rmax0 = fmaxf(rmax0, fmaxf(s[nt][0], s[nt][1]));
            rmax1 = fmaxf(rmax1, fmaxf(s[nt][2], s[nt][3]));
        }
        #pragma unroll
        for (int o = 1; o <= 2; o <<= 1) {
            rmax0 = fmaxf(rmax0, __shfl_xor_sync(0xffffffffu, rmax0, o));
            rmax1 = fmaxf(rmax1, __shfl_xor_sync(0xffffffffu, rmax1, o));
        }
        float mn0 = fmaxf(m0, rmax0), mn1 = fmaxf(m1, rmax1);
        float alpha0 = ex2f((m0 - mn0) * cexp);
        float alpha1 = ex2f((m1 - mn1) * cexp);
        m0 = mn0; m1 = mn1;

        float rs0 = 0.0f, rs1 = 0.0f;
        #pragma unroll
        for (int nt = 0; nt < 8; nt++) {
            s[nt][0] = ex2f((s[nt][0] - mn0) * cexp);
            s[nt][1] = ex2f((s[nt][1] - mn0) * cexp);
            s[nt][2] = ex2f((s[nt][2] - mn1) * cexp);
            s[nt][3] = ex2f((s[nt][3] - mn1) * cexp);
            rs0 += s[nt][0] + s[nt][1];
            rs1 += s[nt][2] + s[nt][3];
        }
        #pragma unroll
        for (int o = 1; o <= 2; o <<= 1) {
            rs0 += __shfl_xor_sync(0xffffffffu, rs0, o);
            rs1 += __shfl_xor_sync(0xffffffffu, rs1, o);
        }
        l0 = l0 * alpha0 + rs0;
        l1 = l1 * alpha1 + rs1;
        #pragma unroll
        for (int nt = 0; nt < 16; nt++) {
            out[nt][0] *= alpha0; out[nt][1] *= alpha0;
            out[nt][2] *= alpha1; out[nt][3] *= alpha1;
        }

        // ---- wait V, then O += P @ V : single product ----
        asm volatile("cp.async.wait_group 0;");
        __syncthreads();

        #pragma unroll
        for (int kk = 0; kk < 4; kk++) {
            uint32_t ph[4];
            #pragma unroll
            for (int half = 0; half < 2; half++) {
                const float* sp = s[2*kk + half];
                #pragma unroll
                for (int rr = 0; rr < 2; rr++)
                    ph[half*2 + rr] = pack_h2(sp[rr*2], sp[rr*2+1]);
            }
            uint32_t vf[8][4];
            uint32_t vb = (uint32_t)((kk * 16 + v_r) * FP + v_c) * 2;
            const uint32_t VN_STRIDE = 16 * 2;
            #pragma unroll
            for (int ng = 0; ng < 8; ng++)
                ldsm4t(vf[ng], su + F_VF + vb + ng * VN_STRIDE);
            #pragma unroll
            for (int ng = 0; ng < 8; ng++) {
                mma16816(out[2*ng],   ph, vf[ng]);
                mma16816(out[2*ng+1], ph, vf[ng] + 2);
            }
        }
    }

    // ---- epilogue: normalize, write single fp16 (B,S,H*HD) ----
    float il0 = 1.0f / l0, il1 = 1.0f / l1;
    const int row0g = q0 + wrow + (lane >> 2);
    const int cl = 2 * (lane & 3);
    #pragma unroll
    for (int ng = 0; ng < 16; ng++) {
        int col = h * HD_ + ng * 8 + cl;
        #pragma unroll
        for (int half = 0; half < 2; half++) {
            int rowg = row0g + half * 8;
            float v0 = out[ng][half*2]     * (half ? il1 : il0);
            float v1 = out[ng][half*2 + 1] * (half ? il1 : il0);
            size_t o = ((size_t)b * S_ + rowg) * (H_ * HD_) + col;
            *(__half2*)&g_af[o] = __floats2half2_rn(v0, v1);
        }
    }
}

// ---------------------------------------------------------------------------
// Launch.
// ---------------------------------------------------------------------------
extern "C" void kernel_launch(void* const* d_in, const int* in_sizes, int n_in,
                              void* d_out, int out_size)
{
    const float* x  = (const float*)d_in[0];
    const float* wq = (const float*)d_in[1];
    const float* wk = (const float*)d_in[2];
    const float* wv = (const float*)d_in[3];
    const float* wo = (const float*)d_in[4];
    const int* pos  = (const int*)d_in[6];

    __half *xf, *wqkv, *wot, *af;
    cudaGetSymbolAddress((void**)&xf, g_xf);
    cudaGetSymbolAddress((void**)&wqkv, g_wqkvt);
    cudaGetSymbolAddress((void**)&wot, g_wot);
    cudaGetSymbolAddress((void**)&af, g_af);

    dim3 blk256(256);

    // [0] preprocessing: weight transposes + rope table + x convert
    preprocess_kernel<<<dim3(64, 64, 6), dim3(32, 8)>>>(
        x, wq, wk, wv, wo, xf, wqkv, wot);

    cudaFuncSetAttribute(hmma_qkv_kernel, cudaFuncAttributeMaxDynamicSharedMemorySize, QKV_SMEM_BYTES);
    cudaFuncSetAttribute(hmma_oproj_kernel, cudaFuncAttributeMaxDynamicSharedMemorySize, O_SMEM_BYTES);

    // [1] persistent merged QKV projection with fused RoPE epilogue
    hmma_qkv_kernel<<<NSM_CTAS, blk256, QKV_SMEM_BYTES>>>(xf, wqkv, pos);

    // [2] flash attention
    cudaFuncSetAttribute(flash_hmma_kernel, cudaFuncAttributeMaxDynamicSharedMemorySize, FA_SMEM_BYTES);
    flash_hmma_kernel<<<dim3(S_ / 64, B_ * H_), 128, FA_SMEM_BYTES>>>();

    // [3] persistent output projection straight into d_out
    hmma_oproj_kernel<<<NSM_CTAS, blk256, O_SMEM_BYTES>>>(af, wot, (float*)d_out);
}

// round 17
// speedup vs baseline: 1.7092x; 1.0550x over previous
#include <cuda_runtime.h>
#include <cuda_fp16.h>
#include <math.h>
#include <cstdint>

#define B_  2
#define S_  2048
#define D_  2048
#define H_  16
#define KV_ 4
#define HD_ 128
#define NQKV 3072   // 2048 q + 512 k + 512 v

#define NSM_CTAS 296     // 2 CTAs/SM x 148 SMs (GEMMs)
#define FLASH_CTAS 444   // 3 CTAs/SM x 148 SMs
#define FLASH_ITEMS (32 * 32)

// ---------------------------------------------------------------------------
// Helpers (base-target instructions only: ldmatrix / mma.sync / cp.async)
// ---------------------------------------------------------------------------
__device__ __forceinline__ uint32_t smem_to_u32(const void* smem_ptr) {
    uint32_t addr;
    asm("{ .reg .u64 tmp; cvta.to.shared.u64 tmp, %1; cvt.u32.u64 %0, tmp; }"
        : "=r"(addr) : "l"(smem_ptr));
    return addr;
}
__device__ __forceinline__ void cp_async16(uint32_t s, const void* g) {
    asm volatile("cp.async.cg.shared.global [%0], [%1], 16;" :: "r"(s), "l"(g));
}
__device__ __forceinline__ void ldsm4(uint32_t* r, uint32_t addr) {
    asm volatile("ldmatrix.sync.aligned.m8n8.x4.shared.b16 {%0,%1,%2,%3}, [%4];"
        : "=r"(r[0]), "=r"(r[1]), "=r"(r[2]), "=r"(r[3]) : "r"(addr));
}
__device__ __forceinline__ void ldsm4t(uint32_t* r, uint32_t addr) {
    asm volatile("ldmatrix.sync.aligned.m8n8.x4.trans.shared.b16 {%0,%1,%2,%3}, [%4];"
        : "=r"(r[0]), "=r"(r[1]), "=r"(r[2]), "=r"(r[3]) : "r"(addr));
}
// fp16 MMA, fp32 accumulate
__device__ __forceinline__ void mma16816(float* d, const uint32_t* a, const uint32_t* b) {
    asm volatile(
        "mma.sync.aligned.m16n8k16.row.col.f32.f16.f16.f32 "
        "{%0,%1,%2,%3}, {%4,%5,%6,%7}, {%8,%9}, {%0,%1,%2,%3};"
        : "+f"(d[0]), "+f"(d[1]), "+f"(d[2]), "+f"(d[3])
        : "r"(a[0]), "r"(a[1]), "r"(a[2]), "r"(a[3]), "r"(b[0]), "r"(b[1]));
}
__device__ __forceinline__ uint32_t pack_h2(float lo, float hi) {
    __half2 t = __floats2half2_rn(lo, hi);
    return *(uint32_t*)&t;
}
__device__ __forceinline__ float ex2f(float x) {
    float r; asm("ex2.approx.f32 %0, %1;" : "=f"(r) : "f"(x)); return r;
}

// ---------------------------------------------------------------------------
// Scratch (allocation-free rule: device globals)
// ---------------------------------------------------------------------------
__device__ __half g_xf[B_*S_*D_];                  // x single fp16
__device__ __half g_wqkvt[NQKV*D_];                // weights fp16 [3072,2048]
__device__ __half g_wot[D_*D_];                    // wo fp16 [N,K]
__device__ __half g_af[B_*S_*H_*HD_];              // attn out fp16

__device__ __half g_qf[B_*H_*S_*HD_];              // roped Q fp16
__device__ __half g_kf[B_*KV_*S_*HD_];             // roped K fp16
__device__ __half g_vf[B_*KV_*S_*HD_];             // V fp16

__device__ float2 g_rope[S_ * (HD_/2)];
__device__ int g_flash_ctr;                        // dynamic work counter

// ---------------------------------------------------------------------------
// Preprocessing mega-kernel, ONE launch:
//   z=0..3: weight transposes (fp32 [K,N] -> fp16 [N,K])
//   z=4:    RoPE cos/sin table   z=5: x fp32 -> fp16 convert
// ---------------------------------------------------------------------------
__global__ void preprocess_kernel(
    const float* __restrict__ x,
    const float* __restrict__ wq, const float* __restrict__ wk,
    const float* __restrict__ wv, const float* __restrict__ wo,
    __half* __restrict__ xf, __half* __restrict__ qkv, __half* __restrict__ wot)
{
    const int z = blockIdx.z;
    const int tid = threadIdx.y * 32 + threadIdx.x;
    if (z == 4) {
        int bid = blockIdx.y * gridDim.x + blockIdx.x;
        int idx = bid * 256 + tid;
        if (idx >= S_ * (HD_/2)) return;
        int i = idx & 63, pos = idx >> 6;
        const double LOG2_THETA = 18.93156856932417108;   // log2(500000)
        double inv = exp2(-((double)i / 64.0) * LOG2_THETA);
        double f = (double)pos * inv;
        const double TWO_PI_HI = 6.283185307179586;
        const double TWO_PI_LO = 2.4492935982947064e-16;
        double n = rint(f * 0.15915494309189535);
        double r = f - n * TWO_PI_HI;
        r = r - n * TWO_PI_LO;
        float rc, rs;
        __sincosf((float)r, &rs, &rc);
        g_rope[idx] = make_float2(rc, rs);
        return;
    }
    if (z == 5) {
        int bid = blockIdx.y * gridDim.x + blockIdx.x;
        const float4* in4 = (const float4*)x;
        __half2* out2 = (__half2*)xf;
        #pragma unroll
        for (int it = 0; it < 2; it++) {
            int i = bid * 512 + it * 256 + tid;
            float4 v = in4[i];
            out2[2*i]   = __floats2half2_rn(v.x, v.y);
            out2[2*i+1] = __floats2half2_rn(v.z, v.w);
        }
        return;
    }
    const float* in;
    __half* oh;
    int N;
    if (z == 0)      { in = wq; oh = qkv;                     N = 2048; }
    else if (z == 1) { in = wk; oh = qkv + (size_t)2048 * D_; N = 512; }
    else if (z == 2) { in = wv; oh = qkv + (size_t)2560 * D_; N = 512; }
    else             { in = wo; oh = wot;                     N = 2048; }
    if (blockIdx.x * 32 >= N) return;

    __shared__ float tile[32][33];
    int tx = threadIdx.x, ty = threadIdx.y;
    int n0 = blockIdx.x * 32, k0 = blockIdx.y * 32;
    #pragma unroll
    for (int j = 0; j < 32; j += 8)
        tile[ty + j][tx] = in[(size_t)(k0 + ty + j) * N + n0 + tx];
    __syncthreads();
    #pragma unroll
    for (int j = 0; j < 32; j += 8) {
        float v = tile[tx][ty + j];
        oh[(size_t)(n0 + ty + j) * D_ + k0 + tx] = __float2half_rn(v);
    }
}

// ---------------------------------------------------------------------------
// Single-product fp16 GEMM mainloop: 128x128 tile, 256 threads, BK=32,
// double-buffered cp.async. acc += A(MxK fp16) @ B(NxK fp16)^T.
// ---------------------------------------------------------------------------
#define PITCH 40
#define TILE_B (128 * PITCH * 2)        // 10240
#define G_OFF_A 0
#define G_OFF_B TILE_B
#define G_STAGE (2 * TILE_B)            // 20480
#define G_PIPE_BYTES (2 * G_STAGE)      // 40960
#define QKV_SMEM_BYTES 69632            // includes 128x132 fp32 RoPE staging
#define O_SMEM_BYTES   G_PIPE_BYTES

__device__ __forceinline__ void gemm_mainloop1(
    const __half* __restrict__ Af, const __half* __restrict__ Bf,
    int K, int row0, int col0, uint32_t su, int tid, float acc[2][8][4])
{
    const int wid = tid >> 5, lane = tid & 31;
    const int warp_m = wid & 3, warp_n = wid >> 2;
    const int nchunks = K >> 5;

    auto prefetch = [&](int ck, int stg) {
        const int k0 = ck << 5;
        const uint32_t sb = su + stg * G_STAGE;
        #pragma unroll
        for (int h = 0; h < 2; h++) {
            int c = tid + h * 256;
            int r = c >> 2, kc = c & 3;
            uint32_t so = (uint32_t)(r * PITCH * 2 + kc * 16);
            cp_async16(sb + G_OFF_A + so, Af + (size_t)(row0 + r) * K + k0 + kc * 8);
            cp_async16(sb + G_OFF_B + so, Bf + (size_t)(col0 + r) * K + k0 + kc * 8);
        }
        asm volatile("cp.async.commit_group;");
    };

    const int r8 = lane & 7, grp = lane >> 3;
    const int a_r = (grp & 1) * 8 + r8;
    const int a_c = (grp >> 1) * 8;
    const int b_r = (grp >> 1) * 8 + r8;
    const int b_c = (grp & 1) * 8;

    prefetch(0, 0);
    for (int ck = 0; ck < nchunks; ck++) {
        if (ck + 1 < nchunks) {
            prefetch(ck + 1, (ck + 1) & 1);
            asm volatile("cp.async.wait_group 1;");
        } else {
            asm volatile("cp.async.wait_group 0;");
        }
        __syncthreads();

        const uint32_t sb = su + (ck & 1) * G_STAGE;
        #pragma unroll
        for (int ks = 0; ks < 2; ks++) {
            const int klo = ks * 16;
            uint32_t af[2][4], bf[4][4];
            #pragma unroll
            for (int mt = 0; mt < 2; mt++)
                ldsm4(af[mt], sb + G_OFF_A +
                      ((warp_m * 32 + mt * 16 + a_r) * PITCH + klo + a_c) * 2);
            #pragma unroll
            for (int np = 0; np < 4; np++)
                ldsm4(bf[np], sb + G_OFF_B +
                      ((warp_n * 64 + np * 16 + b_r) * PITCH + klo + b_c) * 2);
            #pragma unroll
            for (int np = 0; np < 4; np++)
                #pragma unroll
                for (int mt = 0; mt < 2; mt++) {
                    mma16816(acc[mt][2*np],   af[mt], bf[np]);
                    mma16816(acc[mt][2*np+1], af[mt], bf[np] + 2);
                }
        }
        __syncthreads();
    }
}

// ---------------------------------------------------------------------------
// PERSISTENT merged QKV projection GEMM with fused RoPE epilogue.
// ---------------------------------------------------------------------------
#define EP_PITCH 132
#define QKV_NTX 24
#define QKV_NTILES (24 * 32)

__global__ __launch_bounds__(256, 2) void hmma_qkv_kernel(
    const __half* __restrict__ Af, const __half* __restrict__ Bf,
    const int* __restrict__ pos_ids)
{
    extern __shared__ char smem[];
    const uint32_t su = smem_to_u32(smem);
    const int tid = threadIdx.x;
    const int wid = tid >> 5, lane = tid & 31;
    const int warp_m = wid & 3, warp_n = wid >> 2;
    const int r4 = lane >> 2, c2 = (lane & 3) * 2;

    for (int t = blockIdx.x; t < QKV_NTILES; t += gridDim.x) {
        const int row0 = (t / QKV_NTX) * 128;
        const int col0 = (t % QKV_NTX) * 128;

        float acc[2][8][4];
        #pragma unroll
        for (int i = 0; i < 2; i++)
            #pragma unroll
            for (int j = 0; j < 8; j++)
                #pragma unroll
                for (int k = 0; k < 4; k++) acc[i][j][k] = 0.0f;

        gemm_mainloop1(Af, Bf, D_, row0, col0, su, tid, acc);

        const int region = (col0 < 2048) ? 0 : (col0 < 2560 ? 1 : 2);

        if (region == 2) {
            #pragma unroll
            for (int mt = 0; mt < 2; mt++)
                #pragma unroll
                for (int half = 0; half < 2; half++) {
                    int m = row0 + warp_m * 32 + mt * 16 + half * 8 + r4;
                    int bb = m >> 11;
                    int s  = m & (S_ - 1);
                    #pragma unroll
                    for (int nt = 0; nt < 8; nt++) {
                        int n = col0 + warp_n * 64 + nt * 8 + c2;
                        int nn = n - 2560;
                        int hh = nn >> 7, d = nn & 127;
                        size_t o = (((size_t)bb * KV_ + hh) * S_ + s) * HD_ + d;
                        *(__half2*)&g_vf[o] = __floats2half2_rn(
                            acc[mt][nt][half*2], acc[mt][nt][half*2+1]);
                    }
                }
        } else {
            float* tile = (float*)smem;
            #pragma unroll
            for (int mt = 0; mt < 2; mt++)
                #pragma unroll
                for (int half = 0; half < 2; half++) {
                    int r = warp_m * 32 + mt * 16 + half * 8 + r4;
                    #pragma unroll
                    for (int nt = 0; nt < 8; nt++) {
                        int c = warp_n * 64 + nt * 8 + c2;
                        tile[r * EP_PITCH + c]     = acc[mt][nt][half*2];
                        tile[r * EP_PITCH + c + 1] = acc[mt][nt][half*2+1];
                    }
                }
            __syncthreads();

            #pragma unroll
            for (int it = 0; it < 16; it++) {
                int flat = it * 256 + tid;
                int r = flat >> 5;
                int d0 = (flat & 31) * 2;
                int m = row0 + r;
                int bb = m >> 11;
                int s  = m & (S_ - 1);
                int pos = pos_ids[bb * S_ + s];
                float2 cs0 = g_rope[pos * 64 + d0];
                float2 cs1 = g_rope[pos * 64 + d0 + 1];
                float v0 = tile[r * EP_PITCH + d0];
                float v1 = tile[r * EP_PITCH + d0 + 1];
                float w0 = tile[r * EP_PITCH + d0 + 64];
                float w1 = tile[r * EP_PITCH + d0 + 65];
                float o0 = v0 * cs0.x - w0 * cs0.y;
                float o1 = v1 * cs1.x - w1 * cs1.y;
                float p0 = w0 * cs0.x + v0 * cs0.y;
                float p1 = w1 * cs1.x + v1 * cs1.y;

                if (region == 0) {
                    int hh = col0 >> 7;
                    size_t base = (((size_t)bb * H_ + hh) * S_ + s) * HD_;
                    *(__half2*)&g_qf[base + d0]      = __floats2half2_rn(o0, o1);
                    *(__half2*)&g_qf[base + d0 + 64] = __floats2half2_rn(p0, p1);
                } else {
                    int hh = (col0 - 2048) >> 7;
                    size_t base = (((size_t)bb * KV_ + hh) * S_ + s) * HD_;
                    *(__half2*)&g_kf[base + d0]      = __floats2half2_rn(o0, o1);
                    *(__half2*)&g_kf[base + d0 + 64] = __floats2half2_rn(p0, p1);
                }
            }
        }
        __syncthreads();
    }
}

// ---------------------------------------------------------------------------
// PERSISTENT output projection GEMM (single-product) -> fp32 d_out.
// ---------------------------------------------------------------------------
#define O_NTX 16
#define O_NTILES (16 * 32)

__global__ __launch_bounds__(256, 2) void hmma_oproj_kernel(
    const __half* __restrict__ Af, const __half* __restrict__ Bf,
    float* __restrict__ C)
{
    extern __shared__ char smem[];
    const uint32_t su = smem_to_u32(smem);
    const int tid = threadIdx.x;
    const int wid = tid >> 5, lane = tid & 31;
    const int warp_m = wid & 3, warp_n = wid >> 2;
    const int r4 = lane >> 2, c2 = (lane & 3) * 2;

    for (int t = blockIdx.x; t < O_NTILES; t += gridDim.x) {
        const int row0 = (t / O_NTX) * 128;
        const int col0 = (t % O_NTX) * 128;

        float acc[2][8][4];
        #pragma unroll
        for (int i = 0; i < 2; i++)
            #pragma unroll
            for (int j = 0; j < 8; j++)
                #pragma unroll
                for (int k = 0; k < 4; k++) acc[i][j][k] = 0.0f;

        gemm_mainloop1(Af, Bf, D_, row0, col0, su, tid, acc);

        #pragma unroll
        for (int mt = 0; mt < 2; mt++) {
            #pragma unroll
            for (int half = 0; half < 2; half++) {
                int m = row0 + warp_m * 32 + mt * 16 + half * 8 + r4;
                #pragma unroll
                for (int nt = 0; nt < 8; nt++) {
                    int n = col0 + warp_n * 64 + nt * 8 + c2;
                    float2 v;
                    v.x = acc[mt][nt][half * 2 + 0];
                    v.y = acc[mt][nt][half * 2 + 1];
                    *(float2*)&C[(size_t)m * D_ + n] = v;
                }
            }
        }
        __syncthreads();
    }
}

// ---------------------------------------------------------------------------
// PERSISTENT flash attention with dynamic work stealing.
// Items: w in [0,1024); qt = 31 - (w>>5) (longest first); bh = w & 31.
// ---------------------------------------------------------------------------
#define FP 136
#define FT_B 17408
#define F_QF 0
#define F_KF (1 * FT_B)
#define F_VF (2 * FT_B)
#define FA_SMEM_BYTES (3 * FT_B)

__global__ __launch_bounds__(128, 3) void flash_hmma_kernel()
{
    extern __shared__ char smem[];
    const uint32_t su = smem_to_u32(smem);
    const int tid = threadIdx.x;
    const int wid = tid >> 5, lane = tid & 31;
    const int wrow = wid * 16;

    __shared__ int s_item;

    const int r8 = lane & 7, grp = lane >> 3;
    const int a_r = (grp & 1) * 8 + r8;
    const int a_c = (grp >> 1) * 8;
    const int b_r = (grp >> 1) * 8 + r8;
    const int b_c = (grp & 1) * 8;
    const int v_r = (grp & 1) * 8 + r8;
    const int v_c = (grp >> 1) * 8;

    const float cexp = 0.08838834764831845f * 1.4426950408889634f;

    for (;;) {
        if (tid == 0) s_item = atomicAdd(&g_flash_ctr, 1);
        __syncthreads();   // item visible + previous item's smem fully consumed
        const int w = s_item;
        if (w >= FLASH_ITEMS) return;

        const int qt = 31 - (w >> 5);
        const int q0 = qt * 64;
        const int bh = w & 31;
        const int b = bh >> 4, h = bh & 15;
        const int kvh = h >> 2;

        const __half* Qfg = g_qf + (((size_t)b * H_  + h)   * S_ + q0) * HD_;
        const __half* Kfg = g_kf + (((size_t)b * KV_ + kvh) * S_) * HD_;
        const __half* Vfg = g_vf + (((size_t)b * KV_ + kvh) * S_) * HD_;

        #pragma unroll
        for (int it = 0; it < 8; it++) {
            int chunk = it * 128 + tid;
            int r = chunk >> 4, c = (chunk & 15) * 8;
            uint32_t so = (uint32_t)(r * FP + c) * 2;
            cp_async16(su + F_QF + so, Qfg + (size_t)r * HD_ + c);
        }
        asm volatile("cp.async.commit_group;");

        float out[16][4];
        #pragma unroll
        for (int i = 0; i < 16; i++)
            #pragma unroll
            for (int j = 0; j < 4; j++) out[i][j] = 0.0f;
        float m0 = -1e30f, m1 = -1e30f, l0 = 0.0f, l1 = 0.0f;

        const int ktiles = qt + 1;

        for (int kt = 0; kt < ktiles; kt++) {
            const int j0 = kt * 64;
            __syncthreads();
            #pragma unroll
            for (int it = 0; it < 8; it++) {
                int chunk = it * 128 + tid;
                int r = chunk >> 4, c = (chunk & 15) * 8;
                uint32_t so = (uint32_t)(r * FP + c) * 2;
                cp_async16(su + F_KF + so, Kfg + (size_t)(j0 + r) * HD_ + c);
            }
            asm volatile("cp.async.commit_group;");
            #pragma unroll
            for (int it = 0; it < 8; it++) {
                int chunk = it * 128 + tid;
                int r = chunk >> 4, c = (chunk & 15) * 8;
                uint32_t so = (uint32_t)(r * FP + c) * 2;
                cp_async16(su + F_VF + so, Vfg + (size_t)(j0 + r) * HD_ + c);
            }
            asm volatile("cp.async.commit_group;");
            asm volatile("cp.async.wait_group 1;");
            __syncthreads();

            // ---- S = Q @ K^T ----
            float s[8][4];
            #pragma unroll
            for (int i = 0; i < 8; i++)
                #pragma unroll
                for (int j = 0; j < 4; j++) s[i][j] = 0.0f;

            #pragma unroll
            for (int ks = 0; ks < 8; ks++) {
                const int klo = ks * 16;
                uint32_t qf[4], kf[4][4];
                ldsm4(qf, su + F_QF + (uint32_t)((wrow + a_r) * FP + klo + a_c) * 2);
                #pragma unroll
                for (int ng = 0; ng < 4; ng++)
                    ldsm4(kf[ng], su + F_KF +
                          (uint32_t)((ng * 16 + b_r) * FP + klo + b_c) * 2);
                #pragma unroll
                for (int ng = 0; ng < 4; ng++) {
                    mma16816(s[2*ng],   qf, kf[ng]);
                    mma16816(s[2*ng+1], qf, kf[ng] + 2);
                }
            }

            // ---- causal mask (diagonal tile only) ----
            if (kt == ktiles - 1) {
                const int rl0 = wrow + (lane >> 2);
                const int cl  = 2 * (lane & 3);
                #pragma unroll
                for (int nt = 0; nt < 8; nt++) {
                    int c0 = nt * 8 + cl;
                    if (c0 > rl0)     s[nt][0] = -1e30f;
                    if (c0 + 1 > rl0) s[nt][1] = -1e30f;
                    if (c0 > rl0 + 8)     s[nt][2] = -1e30f;
                    if (c0 + 1 > rl0 + 8) s[nt][3] = -1e30f;
                }
            }

            // ---- online softmax ----
            float rmax0 = -1e30f, rmax1 = -1e30f;
            #pragma unroll
            for (int nt = 0; nt < 8; nt++) {
                rmax0 = fmaxf(rmax0, fmaxf(s[nt][0], s[nt][1]));
                rmax1 = fmaxf(rmax1, fmaxf(s[nt][2], s[nt][3]));
            }
            #pragma unroll
            for (int o = 1; o <= 2; o <<= 1) {
                rmax0 = fmaxf(rmax0, __shfl_xor_sync(0xffffffffu, rmax0, o));
                rmax1 = fmaxf(rmax1, __shfl_xor_sync(0xffffffffu, rmax1, o));
            }
            float mn0 = fmaxf(m0, rmax0), mn1 = fmaxf(m1, rmax1);
            float alpha0 = ex2f((m0 - mn0) * cexp);
            float alpha1 = ex2f((m1 - mn1) * cexp);
            m0 = mn0; m1 = mn1;

            float rs0 = 0.0f, rs1 = 0.0f;
            #pragma unroll
            for (int nt = 0; nt < 8; nt++) {
                s[nt][0] = ex2f((s[nt][0] - mn0) * cexp);
                s[nt][1] = ex2f((s[nt][1] - mn0) * cexp);
                s[nt][2] = ex2f((s[nt][2] - mn1) * cexp);
                s[nt][3] = ex2f((s[nt][3] - mn1) * cexp);
                rs0 += s[nt][0] + s[nt][1];
                rs1 += s[nt][2] + s[nt][3];
            }
            #pragma unroll
            for (int o = 1; o <= 2; o <<= 1) {
                rs0 += __shfl_xor_sync(0xffffffffu, rs0, o);
                rs1 += __shfl_xor_sync(0xffffffffu, rs1, o);
            }
            l0 = l0 * alpha0 + rs0;
            l1 = l1 * alpha1 + rs1;
            #pragma unroll
            for (int nt = 0; nt < 16; nt++) {
                out[nt][0] *= alpha0; out[nt][1] *= alpha0;
                out[nt][2] *= alpha1; out[nt][3] *= alpha1;
            }

            // ---- wait V, then O += P @ V ----
            asm volatile("cp.async.wait_group 0;");
            __syncthreads();

            #pragma unroll
            for (int kk = 0; kk < 4; kk++) {
                uint32_t ph[4];
                #pragma unroll
                for (int half = 0; half < 2; half++) {
                    const float* sp = s[2*kk + half];
                    #pragma unroll
                    for (int rr = 0; rr < 2; rr++)
                        ph[half*2 + rr] = pack_h2(sp[rr*2], sp[rr*2+1]);
                }
                uint32_t vf[8][4];
                uint32_t vb = (uint32_t)((kk * 16 + v_r) * FP + v_c) * 2;
                const uint32_t VN_STRIDE = 16 * 2;
                #pragma unroll
                for (int ng = 0; ng < 8; ng++)
                    ldsm4t(vf[ng], su + F_VF + vb + ng * VN_STRIDE);
                #pragma unroll
                for (int ng = 0; ng < 8; ng++) {
                    mma16816(out[2*ng],   ph, vf[ng]);
                    mma16816(out[2*ng+1], ph, vf[ng] + 2);
                }
            }
        }

        // ---- epilogue: normalize, write single fp16 (B,S,H*HD) ----
        float il0 = 1.0f / l0, il1 = 1.0f / l1;
        const int row0g = q0 + wrow + (lane >> 2);
        const int cl = 2 * (lane & 3);
        #pragma unroll
        for (int ng = 0; ng < 16; ng++) {
            int col = h * HD_ + ng * 8 + cl;
            #pragma unroll
            for (int half = 0; half < 2; half++) {
                int rowg = row0g + half * 8;
                float v0 = out[ng][half*2]     * (half ? il1 : il0);
                float v1 = out[ng][half*2 + 1] * (half ? il1 : il0);
                size_t o = ((size_t)b * S_ + rowg) * (H_ * HD_) + col;
                *(__half2*)&g_af[o] = __floats2half2_rn(v0, v1);
            }
        }
    }
}

// ---------------------------------------------------------------------------
// Launch.
// ---------------------------------------------------------------------------
extern "C" void kernel_launch(void* const* d_in, const int* in_sizes, int n_in,
                              void* d_out, int out_size)
{
    const float* x  = (const float*)d_in[0];
    const float* wq = (const float*)d_in[1];
    const float* wk = (const float*)d_in[2];
    const float* wv = (const float*)d_in[3];
    const float* wo = (const float*)d_in[4];
    const int* pos  = (const int*)d_in[6];

    __half *xf, *wqkv, *wot, *af;
    int* ctr;
    cudaGetSymbolAddress((void**)&xf, g_xf);
    cudaGetSymbolAddress((void**)&wqkv, g_wqkvt);
    cudaGetSymbolAddress((void**)&wot, g_wot);
    cudaGetSymbolAddress((void**)&af, g_af);
    cudaGetSymbolAddress((void**)&ctr, g_flash_ctr);

    dim3 blk256(256);

    // [0] reset flash work counter (graph-capturable memset node)
    cudaMemsetAsync(ctr, 0, sizeof(int));

    // [1] preprocessing: weight transposes + rope table + x convert
    preprocess_kernel<<<dim3(64, 64, 6), dim3(32, 8)>>>(
        x, wq, wk, wv, wo, xf, wqkv, wot);

    cudaFuncSetAttribute(hmma_qkv_kernel, cudaFuncAttributeMaxDynamicSharedMemorySize, QKV_SMEM_BYTES);
    cudaFuncSetAttribute(hmma_oproj_kernel, cudaFuncAttributeMaxDynamicSharedMemorySize, O_SMEM_BYTES);

    // [2] persistent merged QKV projection with fused RoPE epilogue
    hmma_qkv_kernel<<<NSM_CTAS, blk256, QKV_SMEM_BYTES>>>(xf, wqkv, pos);

    // [3] persistent flash attention, dynamic work stealing
    cudaFuncSetAttribute(flash_hmma_kernel, cudaFuncAttributeMaxDynamicSharedMemorySize, FA_SMEM_BYTES);
    flash_hmma_kernel<<<FLASH_CTAS, 128, FA_SMEM_BYTES>>>();

    // [4] persistent output projection straight into d_out
    hmma_oproj_kernel<<<NSM_CTAS, blk256, O_SMEM_BYTES>>>(af, wot, (float*)d_out);
}